// round 1
// baseline (speedup 1.0000x reference)
#include <cuda_runtime.h>
#include <math.h>

#define T 4096
#define HD 1024
#define ID 2048
#define NE 8
#define NK 2
#define ROWS_R (T * NK)          /* 8192 routed rows (t*2+k) */
#define ROWS_ALL (ROWS_R + T)    /* + 4096 shared rows       */

#define OUT_AUX ((size_t)T * HD)
#define OUT_Z (OUT_AUX + 1)
#define OUT_LOGITS (OUT_Z + 1)

#define BM 64
#define BN 64
#define BK 16

// ---- device scratch (static: no allocations allowed) ----
__device__ float g_act[(size_t)ROWS_ALL * ID];   // 96 MB: silu(gate)*up
__device__ float g_y[(size_t)ROWS_ALL * HD];     // 48 MB: down-proj output
__device__ int   g_elist[NE * T];                // expert -> list of slots (t*2+k)
__device__ int   g_count[NE];
__device__ float g_wslot[T * NK];                // slot -> normalized top-k weight
__device__ float g_probsum[NE];
__device__ float g_zsum;

// ---- packed f32x2 helpers (FFMA2: 2 FMA / issue slot) ----
static __device__ __forceinline__ unsigned long long pk2(float x, float y) {
    unsigned long long r;
    asm("mov.b64 %0, {%1, %2};" : "=l"(r) : "f"(x), "f"(y));
    return r;
}
static __device__ __forceinline__ void upk2(unsigned long long v, float& x, float& y) {
    asm("mov.b64 {%0, %1}, %2;" : "=f"(x), "=f"(y) : "l"(v));
}
static __device__ __forceinline__ void fma2(unsigned long long& d,
                                            unsigned long long a,
                                            unsigned long long b) {
    asm("fma.rn.f32x2 %0, %1, %2, %3;" : "=l"(d) : "l"(a), "l"(b), "l"(d));
}

// ============================================================
// reset per-launch mutable state (graph replays!)
// ============================================================
__global__ void reset_kernel() {
    int i = threadIdx.x;
    if (i < NE) { g_count[i] = 0; g_probsum[i] = 0.f; }
    if (i == 0) g_zsum = 0.f;
}

// ============================================================
// router: one warp per token
// ============================================================
__global__ void router_kernel(const float* __restrict__ x,
                              const float* __restrict__ rw,
                              float* __restrict__ out) {
    int warp = threadIdx.x >> 5;
    int lane = threadIdx.x & 31;
    int t = blockIdx.x * 4 + warp;
    if (t >= T) return;

    const float* xr = x + (size_t)t * HD;
    float acc[NE];
#pragma unroll
    for (int e = 0; e < NE; e++) acc[e] = 0.f;
    for (int h = lane; h < HD; h += 32) {
        float xv = xr[h];
        const float* r = rw + h * NE;
#pragma unroll
        for (int e = 0; e < NE; e++) acc[e] = fmaf(xv, r[e], acc[e]);
    }
#pragma unroll
    for (int off = 16; off; off >>= 1) {
#pragma unroll
        for (int e = 0; e < NE; e++)
            acc[e] += __shfl_xor_sync(0xffffffffu, acc[e], off);
    }

    if (lane == 0) {
        float m = acc[0];
#pragma unroll
        for (int e = 1; e < NE; e++) m = fmaxf(m, acc[e]);
        float s = 0.f;
#pragma unroll
        for (int e = 0; e < NE; e++) s += expf(acc[e] - m);
        float lse = m + logf(s);
        float p[NE];
#pragma unroll
        for (int e = 0; e < NE; e++) p[e] = expf(acc[e] - lse);

        // top-2, first-occurrence tie break (matches jax.lax.top_k)
        int i0 = 0;
#pragma unroll
        for (int e = 1; e < NE; e++) if (p[e] > p[i0]) i0 = e;
        int i1 = (i0 == 0) ? 1 : 0;
#pragma unroll
        for (int e = 0; e < NE; e++) if (e != i1 && e != i0 && p[e] > p[i1]) i1 = e;

        float sum2 = p[i0] + p[i1];
        g_wslot[2 * t]     = p[i0] / sum2;
        g_wslot[2 * t + 1] = p[i1] / sum2;

        int pos0 = atomicAdd(&g_count[i0], 1);
        g_elist[i0 * T + pos0] = 2 * t;
        int pos1 = atomicAdd(&g_count[i1], 1);
        g_elist[i1 * T + pos1] = 2 * t + 1;

#pragma unroll
        for (int e = 0; e < NE; e++) {
            out[OUT_LOGITS + (size_t)t * NE + e] = acc[e];
            atomicAdd(&g_probsum[e], p[e]);
        }
        atomicAdd(&g_zsum, lse * lse);
    }
}

__global__ void finalize_kernel(float* __restrict__ out) {
    if (threadIdx.x == 0) {
        float aux = 0.f;
#pragma unroll
        for (int e = 0; e < NE; e++)
            aux += ((float)g_count[e] / (2.0f * (float)T)) * (g_probsum[e] / (float)T);
        out[OUT_AUX] = (float)NE * aux;
        out[OUT_Z] = g_zsum / (float)T;
    }
}

// ============================================================
// GEMM1: act[slot, 0:I] = silu(X@Wg) * (X@Wu), grouped by expert
// blockIdx.z: 0..7 routed experts, 8 = shared expert
// ============================================================
__global__ __launch_bounds__(256, 3) void gemm1_kernel(
    const float* __restrict__ x,
    const float* __restrict__ gate_w, const float* __restrict__ up_w,
    const float* __restrict__ sgate_w, const float* __restrict__ sup_w)
{
    __shared__ __align__(16) float As[BM][BK + 1];
    __shared__ __align__(16) float Bg[BK][BN];
    __shared__ __align__(16) float Bu[BK][BN];
    __shared__ int s_slot[BM];
    __shared__ int s_tok[BM];

    int e = blockIdx.z;
    int n = (e < NE) ? g_count[e] : T;
    int row0 = blockIdx.x * BM;
    if (row0 >= n) return;
    int j0 = blockIdx.y * BN;
    int tid = threadIdx.x;

    if (tid < BM) {
        int pos = row0 + tid;
        int slot, tok;
        if (pos < n) {
            if (e < NE) { slot = g_elist[e * T + pos]; tok = slot >> 1; }
            else        { slot = ROWS_R + pos;         tok = pos; }
        } else { slot = -1; tok = 0; }
        s_slot[tid] = slot;
        s_tok[tid] = tok;
    }
    __syncthreads();

    const float* Wg = (e < NE) ? gate_w + (size_t)e * HD * ID : sgate_w;
    const float* Wu = (e < NE) ? up_w   + (size_t)e * HD * ID : sup_w;

    unsigned long long zz = pk2(0.f, 0.f);
    unsigned long long accg[4][2], accu[4][2];
#pragma unroll
    for (int i = 0; i < 4; i++) {
        accg[i][0] = zz; accg[i][1] = zz;
        accu[i][0] = zz; accu[i][1] = zz;
    }

    int ar = tid >> 2;            // 0..63 (A row)
    int aseg = (tid & 3) * 4;     // 0,4,8,12
    int bk = tid >> 4;            // 0..15 (B row)
    int bseg = (tid & 15) * 4;    // 0..60
    int ty4 = (tid >> 4) * 4;
    int tx4 = (tid & 15) * 4;

    for (int kt = 0; kt < HD; kt += BK) {
        float4 av = *(const float4*)(x + (size_t)s_tok[ar] * HD + kt + aseg);
        As[ar][aseg] = av.x; As[ar][aseg + 1] = av.y;
        As[ar][aseg + 2] = av.z; As[ar][aseg + 3] = av.w;
        *(float4*)&Bg[bk][bseg] = *(const float4*)(Wg + (size_t)(kt + bk) * ID + j0 + bseg);
        *(float4*)&Bu[bk][bseg] = *(const float4*)(Wu + (size_t)(kt + bk) * ID + j0 + bseg);
        __syncthreads();

#pragma unroll
        for (int kk = 0; kk < BK; kk++) {
            unsigned long long bg0 = *(const unsigned long long*)&Bg[kk][tx4];
            unsigned long long bg1 = *(const unsigned long long*)&Bg[kk][tx4 + 2];
            unsigned long long bu0 = *(const unsigned long long*)&Bu[kk][tx4];
            unsigned long long bu1 = *(const unsigned long long*)&Bu[kk][tx4 + 2];
#pragma unroll
            for (int i = 0; i < 4; i++) {
                float a = As[ty4 + i][kk];
                unsigned long long a2 = pk2(a, a);
                fma2(accg[i][0], a2, bg0);
                fma2(accg[i][1], a2, bg1);
                fma2(accu[i][0], a2, bu0);
                fma2(accu[i][1], a2, bu1);
            }
        }
        __syncthreads();
    }

#pragma unroll
    for (int i = 0; i < 4; i++) {
        int slot = s_slot[ty4 + i];
        if (slot < 0) continue;
        float g0, g1, g2, g3, u0, u1, u2, u3;
        upk2(accg[i][0], g0, g1); upk2(accg[i][1], g2, g3);
        upk2(accu[i][0], u0, u1); upk2(accu[i][1], u2, u3);
        float* dst = g_act + (size_t)slot * ID + j0 + tx4;
        dst[0] = (g0 * u0) / (1.0f + __expf(-g0));
        dst[1] = (g1 * u1) / (1.0f + __expf(-g1));
        dst[2] = (g2 * u2) / (1.0f + __expf(-g2));
        dst[3] = (g3 * u3) / (1.0f + __expf(-g3));
    }
}

// ============================================================
// GEMM2: y[slot, 0:H] = act[slot] @ Wd[e]
// ============================================================
__global__ __launch_bounds__(256, 3) void gemm2_kernel(
    const float* __restrict__ down_w, const float* __restrict__ sdown_w)
{
    __shared__ __align__(16) float As[BM][BK + 1];
    __shared__ __align__(16) float Bs[BK][BN];
    __shared__ int s_slot[BM];
    __shared__ int s_arow[BM];

    int e = blockIdx.z;
    int n = (e < NE) ? g_count[e] : T;
    int row0 = blockIdx.x * BM;
    if (row0 >= n) return;
    int j0 = blockIdx.y * BN;
    int tid = threadIdx.x;

    if (tid < BM) {
        int pos = row0 + tid;
        int slot;
        if (pos < n) slot = (e < NE) ? g_elist[e * T + pos] : (ROWS_R + pos);
        else         slot = -1;
        s_slot[tid] = slot;
        s_arow[tid] = (slot >= 0) ? slot : 0;
    }
    __syncthreads();

    const float* Wd = (e < NE) ? down_w + (size_t)e * ID * HD : sdown_w;

    unsigned long long zz = pk2(0.f, 0.f);
    unsigned long long acc[4][2];
#pragma unroll
    for (int i = 0; i < 4; i++) { acc[i][0] = zz; acc[i][1] = zz; }

    int ar = tid >> 2;
    int aseg = (tid & 3) * 4;
    int bk = tid >> 4;
    int bseg = (tid & 15) * 4;
    int ty4 = (tid >> 4) * 4;
    int tx4 = (tid & 15) * 4;

    for (int kt = 0; kt < ID; kt += BK) {
        float4 av = *(const float4*)(g_act + (size_t)s_arow[ar] * ID + kt + aseg);
        As[ar][aseg] = av.x; As[ar][aseg + 1] = av.y;
        As[ar][aseg + 2] = av.z; As[ar][aseg + 3] = av.w;
        *(float4*)&Bs[bk][bseg] = *(const float4*)(Wd + (size_t)(kt + bk) * HD + j0 + bseg);
        __syncthreads();

#pragma unroll
        for (int kk = 0; kk < BK; kk++) {
            unsigned long long b0 = *(const unsigned long long*)&Bs[kk][tx4];
            unsigned long long b1 = *(const unsigned long long*)&Bs[kk][tx4 + 2];
#pragma unroll
            for (int i = 0; i < 4; i++) {
                float a = As[ty4 + i][kk];
                unsigned long long a2 = pk2(a, a);
                fma2(acc[i][0], a2, b0);
                fma2(acc[i][1], a2, b1);
            }
        }
        __syncthreads();
    }

#pragma unroll
    for (int i = 0; i < 4; i++) {
        int slot = s_slot[ty4 + i];
        if (slot < 0) continue;
        float v0, v1, v2, v3;
        upk2(acc[i][0], v0, v1); upk2(acc[i][1], v2, v3);
        float* dst = g_y + (size_t)slot * HD + j0 + tx4;
        dst[0] = v0; dst[1] = v1; dst[2] = v2; dst[3] = v3;
    }
}

// ============================================================
// combine: out[t] = w0*y[2t] + w1*y[2t+1] + y_shared[t]
// ============================================================
__global__ void combine_kernel(float* __restrict__ out) {
    int idx = blockIdx.x * blockDim.x + threadIdx.x;   // over T*HD/4
    int t = idx / (HD / 4);
    int c = (idx % (HD / 4)) * 4;
    float w0 = g_wslot[2 * t];
    float w1 = g_wslot[2 * t + 1];
    float4 y0 = *(const float4*)(g_y + (size_t)(2 * t) * HD + c);
    float4 y1 = *(const float4*)(g_y + (size_t)(2 * t + 1) * HD + c);
    float4 ys = *(const float4*)(g_y + (size_t)(ROWS_R + t) * HD + c);
    float4 r;
    r.x = fmaf(w0, y0.x, fmaf(w1, y1.x, ys.x));
    r.y = fmaf(w0, y0.y, fmaf(w1, y1.y, ys.y));
    r.z = fmaf(w0, y0.z, fmaf(w1, y1.z, ys.z));
    r.w = fmaf(w0, y0.w, fmaf(w1, y1.w, ys.w));
    *(float4*)(out + (size_t)t * HD + c) = r;
}

// ============================================================
extern "C" void kernel_launch(void* const* d_in, const int* in_sizes, int n_in,
                              void* d_out, int out_size) {
    const float* x   = (const float*)d_in[0];
    const float* rw  = (const float*)d_in[1];
    const float* gw  = (const float*)d_in[2];
    const float* uw  = (const float*)d_in[3];
    const float* dw  = (const float*)d_in[4];
    const float* sgw = (const float*)d_in[5];
    const float* suw = (const float*)d_in[6];
    const float* sdw = (const float*)d_in[7];
    float* out = (float*)d_out;

    reset_kernel<<<1, 32>>>();
    router_kernel<<<T / 4, 128>>>(x, rw, out);
    finalize_kernel<<<1, 1>>>(out);
    gemm1_kernel<<<dim3(T / BM, ID / BN, NE + 1), 256>>>(x, gw, uw, sgw, suw);
    gemm2_kernel<<<dim3(T / BM, HD / BN, NE + 1), 256>>>(dw, sdw);
    combine_kernel<<<(T * HD / 4) / 256, 256>>>(out);
}

// round 2
// speedup vs baseline: 1.0349x; 1.0349x over previous
#include <cuda_runtime.h>
#include <math.h>

#define T 4096
#define HD 1024
#define ID 2048
#define NE 8
#define NK 2
#define ROWS_R (T * NK)          /* 8192 routed rows (t*2+k) */
#define ROWS_ALL (ROWS_R + T)    /* + 4096 shared rows       */

#define OUT_AUX ((size_t)T * HD)
#define OUT_Z (OUT_AUX + 1)
#define OUT_LOGITS (OUT_Z + 1)

#define BM 128
#define BK 16

typedef unsigned long long u64;

// ---- device scratch (static: no allocations allowed) ----
__device__ float g_act[(size_t)ROWS_ALL * ID];   // 96 MB: silu(gate)*up
__device__ float g_y[(size_t)ROWS_ALL * HD];     // 48 MB: down-proj output
__device__ int   g_elist[NE * T];                // expert -> list of slots (t*2+k)
__device__ int   g_count[NE];
__device__ float g_wslot[T * NK];                // slot -> normalized top-k weight
__device__ float g_probsum[NE];
__device__ float g_zsum;

// ---- packed f32x2 helpers ----
static __device__ __forceinline__ u64 pk2(float x, float y) {
    u64 r;
    asm("mov.b64 %0, {%1, %2};" : "=l"(r) : "f"(x), "f"(y));
    return r;
}
static __device__ __forceinline__ void upk2(u64 v, float& x, float& y) {
    asm("mov.b64 {%0, %1}, %2;" : "=f"(x), "=f"(y) : "l"(v));
}
static __device__ __forceinline__ void fma2(u64& d, u64 a, u64 b) {
    asm("fma.rn.f32x2 %0, %1, %2, %3;" : "=l"(d) : "l"(a), "l"(b), "l"(d));
}

// ============================================================
// reset per-launch mutable state (graph replays!)
// ============================================================
__global__ void reset_kernel() {
    int i = threadIdx.x;
    if (i < NE) { g_count[i] = 0; g_probsum[i] = 0.f; }
    if (i == 0) g_zsum = 0.f;
}

// ============================================================
// router: one warp per token
// ============================================================
__global__ void router_kernel(const float* __restrict__ x,
                              const float* __restrict__ rw,
                              float* __restrict__ out) {
    int warp = threadIdx.x >> 5;
    int lane = threadIdx.x & 31;
    int t = blockIdx.x * 4 + warp;
    if (t >= T) return;

    const float* xr = x + (size_t)t * HD;
    float acc[NE];
#pragma unroll
    for (int e = 0; e < NE; e++) acc[e] = 0.f;
    for (int h = lane; h < HD; h += 32) {
        float xv = xr[h];
        const float* r = rw + h * NE;
#pragma unroll
        for (int e = 0; e < NE; e++) acc[e] = fmaf(xv, r[e], acc[e]);
    }
#pragma unroll
    for (int off = 16; off; off >>= 1) {
#pragma unroll
        for (int e = 0; e < NE; e++)
            acc[e] += __shfl_xor_sync(0xffffffffu, acc[e], off);
    }

    if (lane == 0) {
        float m = acc[0];
#pragma unroll
        for (int e = 1; e < NE; e++) m = fmaxf(m, acc[e]);
        float s = 0.f;
#pragma unroll
        for (int e = 0; e < NE; e++) s += expf(acc[e] - m);
        float lse = m + logf(s);
        float p[NE];
#pragma unroll
        for (int e = 0; e < NE; e++) p[e] = expf(acc[e] - lse);

        // top-2, first-occurrence tie break (matches jax.lax.top_k)
        int i0 = 0;
#pragma unroll
        for (int e = 1; e < NE; e++) if (p[e] > p[i0]) i0 = e;
        int i1 = (i0 == 0) ? 1 : 0;
#pragma unroll
        for (int e = 0; e < NE; e++) if (e != i1 && e != i0 && p[e] > p[i1]) i1 = e;

        float sum2 = p[i0] + p[i1];
        g_wslot[2 * t]     = p[i0] / sum2;
        g_wslot[2 * t + 1] = p[i1] / sum2;

        int pos0 = atomicAdd(&g_count[i0], 1);
        g_elist[i0 * T + pos0] = 2 * t;
        int pos1 = atomicAdd(&g_count[i1], 1);
        g_elist[i1 * T + pos1] = 2 * t + 1;

#pragma unroll
        for (int e = 0; e < NE; e++) {
            out[OUT_LOGITS + (size_t)t * NE + e] = acc[e];
            atomicAdd(&g_probsum[e], p[e]);
        }
        atomicAdd(&g_zsum, lse * lse);
    }
}

__global__ void finalize_kernel(float* __restrict__ out) {
    if (threadIdx.x == 0) {
        float aux = 0.f;
#pragma unroll
        for (int e = 0; e < NE; e++)
            aux += ((float)g_count[e] / (2.0f * (float)T)) * (g_probsum[e] / (float)T);
        out[OUT_AUX] = (float)NE * aux;
        out[OUT_Z] = g_zsum / (float)T;
    }
}

// ============================================================
// GEMM1: act[slot, :] = silu(X@Wg) * (X@Wu), grouped by expert.
// BM=128, BN=64, BK=16; 256 threads; thread tile = 8 rows x 4 cols (dual mat).
// A stored in smem as duplicated f32 pairs for direct FFMA2 broadcast LDS.64.
// ============================================================
__global__ __launch_bounds__(256, 2) void gemm1_kernel(
    const float* __restrict__ x,
    const float* __restrict__ gate_w, const float* __restrict__ up_w,
    const float* __restrict__ sgate_w, const float* __restrict__ sup_w)
{
    __shared__ __align__(16) float As2[BK][2 * BM];   // 16 KB, duplicated pairs
    __shared__ __align__(16) float Bg[BK][64];        // 4 KB
    __shared__ __align__(16) float Bu[BK][64];        // 4 KB
    __shared__ int s_slot[BM];
    __shared__ int s_tok[BM];

    int e = blockIdx.z;
    int n = (e < NE) ? g_count[e] : T;
    int row0 = blockIdx.x * BM;
    if (row0 >= n) return;
    int j0 = blockIdx.y * 64;
    int tid = threadIdx.x;

    if (tid < BM) {
        int pos = row0 + tid;
        int slot, tok;
        if (pos < n) {
            if (e < NE) { slot = g_elist[e * T + pos]; tok = slot >> 1; }
            else        { slot = ROWS_R + pos;         tok = pos; }
        } else { slot = -1; tok = 0; }
        s_slot[tid] = slot;
        s_tok[tid] = tok;
    }
    __syncthreads();

    const float* Wg = (e < NE) ? gate_w + (size_t)e * HD * ID : sgate_w;
    const float* Wu = (e < NE) ? up_w   + (size_t)e * HD * ID : sup_w;

    // loader indices: A: 512 float4 -> 2 per thread
    int arow0 = tid >> 2;          // 0..63
    int akseg0 = (tid & 3) * 4;
    int arow1 = arow0 + 64;        // 64..127
    int tokA0 = s_tok[arow0];
    int tokA1 = s_tok[arow1];
    // B: 256 float4 -> 1 per thread (each matrix)
    int brow = tid >> 4;           // 0..15
    int bcol = (tid & 15) * 4;

    int tx4 = (tid & 15) * 4;
    int ty4 = (tid >> 4) * 4;      // rows ty4..ty4+3 and 64+ty4..64+ty4+3

    u64 zz = pk2(0.f, 0.f);
    u64 accg[8][2], accu[8][2];
#pragma unroll
    for (int i = 0; i < 8; i++) {
        accg[i][0] = zz; accg[i][1] = zz;
        accu[i][0] = zz; accu[i][1] = zz;
    }

    // prefetch ktile 0
    float4 pa0 = *(const float4*)(x + (size_t)tokA0 * HD + akseg0);
    float4 pa1 = *(const float4*)(x + (size_t)tokA1 * HD + akseg0);
    float4 pbg = *(const float4*)(Wg + (size_t)brow * ID + j0 + bcol);
    float4 pbu = *(const float4*)(Wu + (size_t)brow * ID + j0 + bcol);

    for (int kt = 0; kt < HD; kt += BK) {
        // store current tile to smem (A duplicated)
        *(u64*)&As2[akseg0 + 0][2 * arow0] = pk2(pa0.x, pa0.x);
        *(u64*)&As2[akseg0 + 1][2 * arow0] = pk2(pa0.y, pa0.y);
        *(u64*)&As2[akseg0 + 2][2 * arow0] = pk2(pa0.z, pa0.z);
        *(u64*)&As2[akseg0 + 3][2 * arow0] = pk2(pa0.w, pa0.w);
        *(u64*)&As2[akseg0 + 0][2 * arow1] = pk2(pa1.x, pa1.x);
        *(u64*)&As2[akseg0 + 1][2 * arow1] = pk2(pa1.y, pa1.y);
        *(u64*)&As2[akseg0 + 2][2 * arow1] = pk2(pa1.z, pa1.z);
        *(u64*)&As2[akseg0 + 3][2 * arow1] = pk2(pa1.w, pa1.w);
        *(float4*)&Bg[brow][bcol] = pbg;
        *(float4*)&Bu[brow][bcol] = pbu;
        __syncthreads();

        // prefetch next ktile
        int ktn = kt + BK;
        if (ktn < HD) {
            pa0 = *(const float4*)(x + (size_t)tokA0 * HD + ktn + akseg0);
            pa1 = *(const float4*)(x + (size_t)tokA1 * HD + ktn + akseg0);
            pbg = *(const float4*)(Wg + (size_t)(ktn + brow) * ID + j0 + bcol);
            pbu = *(const float4*)(Wu + (size_t)(ktn + brow) * ID + j0 + bcol);
        }

#pragma unroll
        for (int kk = 0; kk < BK; kk++) {
            ulonglong2 vg = *(const ulonglong2*)&Bg[kk][tx4];
            ulonglong2 vu = *(const ulonglong2*)&Bu[kk][tx4];
            u64 a[8];
#pragma unroll
            for (int i = 0; i < 4; i++) {
                a[i]     = *(const u64*)&As2[kk][2 * (ty4 + i)];
                a[i + 4] = *(const u64*)&As2[kk][2 * (64 + ty4 + i)];
            }
#pragma unroll
            for (int i = 0; i < 8; i++) {
                fma2(accg[i][0], a[i], vg.x);
                fma2(accg[i][1], a[i], vg.y);
                fma2(accu[i][0], a[i], vu.x);
                fma2(accu[i][1], a[i], vu.y);
            }
        }
        __syncthreads();
    }

#pragma unroll
    for (int i = 0; i < 8; i++) {
        int r = (i < 4) ? (ty4 + i) : (64 + ty4 + i - 4);
        int slot = s_slot[r];
        if (slot < 0) continue;
        float g0, g1, g2, g3, u0, u1, u2, u3;
        upk2(accg[i][0], g0, g1); upk2(accg[i][1], g2, g3);
        upk2(accu[i][0], u0, u1); upk2(accu[i][1], u2, u3);
        float* dst = g_act + (size_t)slot * ID + j0 + tx4;
        dst[0] = (g0 * u0) / (1.0f + __expf(-g0));
        dst[1] = (g1 * u1) / (1.0f + __expf(-g1));
        dst[2] = (g2 * u2) / (1.0f + __expf(-g2));
        dst[3] = (g3 * u3) / (1.0f + __expf(-g3));
    }
}

// ============================================================
// GEMM2: y[slot, :] = act[slot] @ Wd[e].
// BM=128, BN=128, BK=16; 256 threads; thread tile 8x8 (split cols).
// ============================================================
__global__ __launch_bounds__(256, 2) void gemm2_kernel(
    const float* __restrict__ down_w, const float* __restrict__ sdown_w)
{
    __shared__ __align__(16) float As2[BK][2 * BM];   // 16 KB duplicated
    __shared__ __align__(16) float Bs[BK][128];       // 8 KB
    __shared__ int s_slot[BM];
    __shared__ int s_arow[BM];

    int e = blockIdx.z;
    int n = (e < NE) ? g_count[e] : T;
    int row0 = blockIdx.x * BM;
    if (row0 >= n) return;
    int j0 = blockIdx.y * 128;
    int tid = threadIdx.x;

    if (tid < BM) {
        int pos = row0 + tid;
        int slot;
        if (pos < n) slot = (e < NE) ? g_elist[e * T + pos] : (ROWS_R + pos);
        else         slot = -1;
        s_slot[tid] = slot;
        s_arow[tid] = (slot >= 0) ? slot : 0;
    }
    __syncthreads();

    const float* Wd = (e < NE) ? down_w + (size_t)e * ID * HD : sdown_w;

    int arow0 = tid >> 2;
    int akseg0 = (tid & 3) * 4;
    int arow1 = arow0 + 64;
    int srcA0 = s_arow[arow0];
    int srcA1 = s_arow[arow1];
    // B: 512 float4 -> 2 per thread
    int brow0 = tid >> 5;              // 0..7
    int bcol0 = (tid & 31) * 4;        // 0..124
    int brow1 = brow0 + 8;             // 8..15

    int tx4 = (tid & 15) * 4;
    int ty4 = (tid >> 4) * 4;

    u64 zz = pk2(0.f, 0.f);
    u64 acc[8][4];
#pragma unroll
    for (int i = 0; i < 8; i++) {
        acc[i][0] = zz; acc[i][1] = zz; acc[i][2] = zz; acc[i][3] = zz;
    }

    float4 pa0 = *(const float4*)(g_act + (size_t)srcA0 * ID + akseg0);
    float4 pa1 = *(const float4*)(g_act + (size_t)srcA1 * ID + akseg0);
    float4 pb0 = *(const float4*)(Wd + (size_t)brow0 * HD + j0 + bcol0);
    float4 pb1 = *(const float4*)(Wd + (size_t)brow1 * HD + j0 + bcol0);

    for (int kt = 0; kt < ID; kt += BK) {
        *(u64*)&As2[akseg0 + 0][2 * arow0] = pk2(pa0.x, pa0.x);
        *(u64*)&As2[akseg0 + 1][2 * arow0] = pk2(pa0.y, pa0.y);
        *(u64*)&As2[akseg0 + 2][2 * arow0] = pk2(pa0.z, pa0.z);
        *(u64*)&As2[akseg0 + 3][2 * arow0] = pk2(pa0.w, pa0.w);
        *(u64*)&As2[akseg0 + 0][2 * arow1] = pk2(pa1.x, pa1.x);
        *(u64*)&As2[akseg0 + 1][2 * arow1] = pk2(pa1.y, pa1.y);
        *(u64*)&As2[akseg0 + 2][2 * arow1] = pk2(pa1.z, pa1.z);
        *(u64*)&As2[akseg0 + 3][2 * arow1] = pk2(pa1.w, pa1.w);
        *(float4*)&Bs[brow0][bcol0] = pb0;
        *(float4*)&Bs[brow1][bcol0] = pb1;
        __syncthreads();

        int ktn = kt + BK;
        if (ktn < ID) {
            pa0 = *(const float4*)(g_act + (size_t)srcA0 * ID + ktn + akseg0);
            pa1 = *(const float4*)(g_act + (size_t)srcA1 * ID + ktn + akseg0);
            pb0 = *(const float4*)(Wd + (size_t)(ktn + brow0) * HD + j0 + bcol0);
            pb1 = *(const float4*)(Wd + (size_t)(ktn + brow1) * HD + j0 + bcol0);
        }

#pragma unroll
        for (int kk = 0; kk < BK; kk++) {
            ulonglong2 b0 = *(const ulonglong2*)&Bs[kk][tx4];
            ulonglong2 b1 = *(const ulonglong2*)&Bs[kk][64 + tx4];
            u64 a[8];
#pragma unroll
            for (int i = 0; i < 4; i++) {
                a[i]     = *(const u64*)&As2[kk][2 * (ty4 + i)];
                a[i + 4] = *(const u64*)&As2[kk][2 * (64 + ty4 + i)];
            }
#pragma unroll
            for (int i = 0; i < 8; i++) {
                fma2(acc[i][0], a[i], b0.x);
                fma2(acc[i][1], a[i], b0.y);
                fma2(acc[i][2], a[i], b1.x);
                fma2(acc[i][3], a[i], b1.y);
            }
        }
        __syncthreads();
    }

#pragma unroll
    for (int i = 0; i < 8; i++) {
        int r = (i < 4) ? (ty4 + i) : (64 + ty4 + i - 4);
        int slot = s_slot[r];
        if (slot < 0) continue;
        float v0, v1, v2, v3;
        float* dst = g_y + (size_t)slot * HD + j0;
        upk2(acc[i][0], v0, v1); upk2(acc[i][1], v2, v3);
        dst[tx4 + 0] = v0; dst[tx4 + 1] = v1; dst[tx4 + 2] = v2; dst[tx4 + 3] = v3;
        upk2(acc[i][2], v0, v1); upk2(acc[i][3], v2, v3);
        dst[64 + tx4 + 0] = v0; dst[64 + tx4 + 1] = v1;
        dst[64 + tx4 + 2] = v2; dst[64 + tx4 + 3] = v3;
    }
}

// ============================================================
// combine: out[t] = w0*y[2t] + w1*y[2t+1] + y_shared[t]
// ============================================================
__global__ void combine_kernel(float* __restrict__ out) {
    int idx = blockIdx.x * blockDim.x + threadIdx.x;   // over T*HD/4
    int t = idx / (HD / 4);
    int c = (idx % (HD / 4)) * 4;
    float w0 = g_wslot[2 * t];
    float w1 = g_wslot[2 * t + 1];
    float4 y0 = *(const float4*)(g_y + (size_t)(2 * t) * HD + c);
    float4 y1 = *(const float4*)(g_y + (size_t)(2 * t + 1) * HD + c);
    float4 ys = *(const float4*)(g_y + (size_t)(ROWS_R + t) * HD + c);
    float4 r;
    r.x = fmaf(w0, y0.x, fmaf(w1, y1.x, ys.x));
    r.y = fmaf(w0, y0.y, fmaf(w1, y1.y, ys.y));
    r.z = fmaf(w0, y0.z, fmaf(w1, y1.z, ys.z));
    r.w = fmaf(w0, y0.w, fmaf(w1, y1.w, ys.w));
    *(float4*)(out + (size_t)t * HD + c) = r;
}

// ============================================================
extern "C" void kernel_launch(void* const* d_in, const int* in_sizes, int n_in,
                              void* d_out, int out_size) {
    const float* x   = (const float*)d_in[0];
    const float* rw  = (const float*)d_in[1];
    const float* gw  = (const float*)d_in[2];
    const float* uw  = (const float*)d_in[3];
    const float* dw  = (const float*)d_in[4];
    const float* sgw = (const float*)d_in[5];
    const float* suw = (const float*)d_in[6];
    const float* sdw = (const float*)d_in[7];
    float* out = (float*)d_out;

    reset_kernel<<<1, 32>>>();
    router_kernel<<<T / 4, 128>>>(x, rw, out);
    finalize_kernel<<<1, 1>>>(out);
    gemm1_kernel<<<dim3(T / BM, ID / 64, NE + 1), 256>>>(x, gw, uw, sgw, suw);
    gemm2_kernel<<<dim3(T / BM, HD / 128, NE + 1), 256>>>(dw, sdw);
    combine_kernel<<<(T * HD / 4) / 256, 256>>>(out);
}

// round 7
// speedup vs baseline: 2.1092x; 2.0381x over previous
#include <cuda_runtime.h>
#include <cuda_bf16.h>
#include <math.h>
#include <cstdint>

#define T 4096
#define HD 1024
#define ID 2048
#define NE 8
#define NK 2
#define ROWS_R (T * NK)          /* 8192 routed rows (t*2+k) */
#define ROWS_ALL (ROWS_R + T)    /* + 4096 shared rows       */

#define OUT_AUX ((size_t)T * HD)
#define OUT_Z (OUT_AUX + 1)
#define OUT_LOGITS (OUT_Z + 1)

#define BM 128
#define BKC 32                   /* k-chunk (bf16 elems) = 64 bytes */
#define NC1 (HD / BKC)           /* 32 iters gemm1 */
#define NC2 (ID / BKC)           /* 64 iters gemm2 */
#define RSB 80                   /* smem row stride bytes (40 bf16) */

// smem plane sizes: 128 rows * 80B = 10240 per plane
#define PL 10240
#define BUFB (4 * PL)            /* Ah Al Bh Bl = 40960 */
#define SM_TOK 0
#define SM_SLOT 512
#define SM_BUF0 1024
#define SMEM_BYTES (1024 + 2 * BUFB)   /* 82944 */

typedef unsigned long long u64;

// ---------------- device scratch (static; no allocs allowed) ----------------
__device__ __nv_bfloat16 g_wgh[(size_t)9 * ID * HD];
__device__ __nv_bfloat16 g_wgl[(size_t)9 * ID * HD];
__device__ __nv_bfloat16 g_wuh[(size_t)9 * ID * HD];
__device__ __nv_bfloat16 g_wul[(size_t)9 * ID * HD];
__device__ __nv_bfloat16 g_wdh[(size_t)9 * HD * ID];
__device__ __nv_bfloat16 g_wdl[(size_t)9 * HD * ID];
__device__ __nv_bfloat16 g_xh[(size_t)T * HD];
__device__ __nv_bfloat16 g_xl[(size_t)T * HD];
__device__ __nv_bfloat16 g_acth[(size_t)ROWS_ALL * ID];
__device__ __nv_bfloat16 g_actl[(size_t)ROWS_ALL * ID];
__device__ float g_y[(size_t)ROWS_ALL * HD];
__device__ int   g_elist[NE * T];
__device__ int   g_count[NE];
__device__ float g_wslot[T * NK];
__device__ float g_probsum[NE];
__device__ float g_zsum;

// ---------------- PTX helpers (plain sm_103-safe) ----------------
static __device__ __forceinline__ uint32_t s2u(const void* p) {
    uint32_t a;
    asm("{ .reg .u64 t; cvta.to.shared.u64 t, %1; cvt.u32.u64 %0, t; }"
        : "=r"(a) : "l"(p));
    return a;
}

#define CPA16(sa, ga) \
    asm volatile("cp.async.cg.shared.global [%0], [%1], 16;" \
        :: "r"((uint32_t)(sa)), "l"(ga) : "memory")
#define CP_COMMIT() asm volatile("cp.async.commit_group;" ::: "memory")
#define CP_WAIT1()  asm volatile("cp.async.wait_group 1;" ::: "memory")

static __device__ __forceinline__ void ldsm4(uint32_t* r, uint32_t a) {
    asm volatile("ldmatrix.sync.aligned.m8n8.x4.shared.b16 {%0,%1,%2,%3}, [%4];"
        : "=r"(r[0]), "=r"(r[1]), "=r"(r[2]), "=r"(r[3]) : "r"(a));
}

static __device__ __forceinline__ void mma16816(float* d, const uint32_t* a,
                                                const uint32_t* b) {
    asm volatile(
        "mma.sync.aligned.m16n8k16.row.col.f32.bf16.bf16.f32 "
        "{%0,%1,%2,%3}, {%4,%5,%6,%7}, {%8,%9}, {%0,%1,%2,%3};"
        : "+f"(d[0]), "+f"(d[1]), "+f"(d[2]), "+f"(d[3])
        : "r"(a[0]), "r"(a[1]), "r"(a[2]), "r"(a[3]), "r"(b[0]), "r"(b[1]));
}

// ============================================================
__global__ void reset_kernel() {
    int i = threadIdx.x;
    if (i < NE) { g_count[i] = 0; g_probsum[i] = 0.f; }
    if (i == 0) g_zsum = 0.f;
}

// ============================================================
// convert x -> bf16 hi/lo planes
// ============================================================
__global__ void convx_kernel(const float* __restrict__ x) {
    size_t i = ((size_t)blockIdx.x * blockDim.x + threadIdx.x) * 4;
    float4 v = *(const float4*)(x + i);
    __nv_bfloat16 h0 = __float2bfloat16(v.x), h1 = __float2bfloat16(v.y);
    __nv_bfloat16 h2 = __float2bfloat16(v.z), h3 = __float2bfloat16(v.w);
    __nv_bfloat162 p0, p1, q0, q1;
    p0.x = h0; p0.y = h1; p1.x = h2; p1.y = h3;
    q0.x = __float2bfloat16(v.x - __bfloat162float(h0));
    q0.y = __float2bfloat16(v.y - __bfloat162float(h1));
    q1.x = __float2bfloat16(v.z - __bfloat162float(h2));
    q1.y = __float2bfloat16(v.w - __bfloat162float(h3));
    *(__nv_bfloat162*)(g_xh + i) = p0;
    *(__nv_bfloat162*)(g_xh + i + 2) = p1;
    *(__nv_bfloat162*)(g_xl + i) = q0;
    *(__nv_bfloat162*)(g_xl + i + 2) = q1;
}

// ============================================================
// convert + transpose weights: src [K][N] fp32 -> dst [e][N][K] bf16 hi/lo
// ============================================================
__global__ void convw_kernel(const float* __restrict__ wr,
                             const float* __restrict__ ws,
                             int which, int K, int N) {
    __nv_bfloat16 *dh, *dl;
    if (which == 0)      { dh = g_wgh; dl = g_wgl; }
    else if (which == 1) { dh = g_wuh; dl = g_wul; }
    else                 { dh = g_wdh; dl = g_wdl; }
    int e = blockIdx.z;
    const float* src = (e < NE) ? (wr + (size_t)e * K * N) : ws;
    __shared__ float tile[32][33];
    int n0 = blockIdx.x * 32, k0 = blockIdx.y * 32;
    int tx = threadIdx.x;
    for (int i = threadIdx.y; i < 32; i += 8)
        tile[i][tx] = src[(size_t)(k0 + i) * N + n0 + tx];
    __syncthreads();
    size_t base = (size_t)e * K * N;
    for (int i = threadIdx.y; i < 32; i += 8) {
        float v = tile[tx][i];
        __nv_bfloat16 h = __float2bfloat16(v);
        size_t o = base + (size_t)(n0 + i) * K + k0 + tx;
        dh[o] = h;
        dl[o] = __float2bfloat16(v - __bfloat162float(h));
    }
}

// ============================================================
// router: one warp per token
// ============================================================
__global__ void router_kernel(const float* __restrict__ x,
                              const float* __restrict__ rw,
                              float* __restrict__ out) {
    int warp = threadIdx.x >> 5;
    int lane = threadIdx.x & 31;
    int t = blockIdx.x * 4 + warp;
    if (t >= T) return;

    const float* xr = x + (size_t)t * HD;
    float acc[NE];
#pragma unroll
    for (int e = 0; e < NE; e++) acc[e] = 0.f;
    for (int h = lane; h < HD; h += 32) {
        float xv = xr[h];
        const float* r = rw + h * NE;
#pragma unroll
        for (int e = 0; e < NE; e++) acc[e] = fmaf(xv, r[e], acc[e]);
    }
#pragma unroll
    for (int off = 16; off; off >>= 1) {
#pragma unroll
        for (int e = 0; e < NE; e++)
            acc[e] += __shfl_xor_sync(0xffffffffu, acc[e], off);
    }

    if (lane == 0) {
        float m = acc[0];
#pragma unroll
        for (int e = 1; e < NE; e++) m = fmaxf(m, acc[e]);
        float s = 0.f;
#pragma unroll
        for (int e = 0; e < NE; e++) s += expf(acc[e] - m);
        float lse = m + logf(s);
        float p[NE];
#pragma unroll
        for (int e = 0; e < NE; e++) p[e] = expf(acc[e] - lse);

        int i0 = 0;
#pragma unroll
        for (int e = 1; e < NE; e++) if (p[e] > p[i0]) i0 = e;
        int i1 = (i0 == 0) ? 1 : 0;
#pragma unroll
        for (int e = 0; e < NE; e++) if (e != i1 && e != i0 && p[e] > p[i1]) i1 = e;

        float sum2 = p[i0] + p[i1];
        g_wslot[2 * t]     = p[i0] / sum2;
        g_wslot[2 * t + 1] = p[i1] / sum2;

        int pos0 = atomicAdd(&g_count[i0], 1);
        g_elist[i0 * T + pos0] = 2 * t;
        int pos1 = atomicAdd(&g_count[i1], 1);
        g_elist[i1 * T + pos1] = 2 * t + 1;

#pragma unroll
        for (int e = 0; e < NE; e++) {
            out[OUT_LOGITS + (size_t)t * NE + e] = acc[e];
            atomicAdd(&g_probsum[e], p[e]);
        }
        atomicAdd(&g_zsum, lse * lse);
    }
}

__global__ void finalize_kernel(float* __restrict__ out) {
    if (threadIdx.x == 0) {
        float aux = 0.f;
#pragma unroll
        for (int e = 0; e < NE; e++)
            aux += ((float)g_count[e] / (2.0f * (float)T)) * (g_probsum[e] / (float)T);
        out[OUT_AUX] = (float)NE * aux;
        out[OUT_Z] = g_zsum / (float)T;
    }
}

// ============================================================
// GEMM1 (mma.sync bf16 3-term split): per CTA 128 rows x 64 cols of
// BOTH gate and up; fused SiLU epilogue -> g_acth/g_actl.
// smem buffer: Ah | Al | B(gate 0-63, up 64-127)h | Bl
// ============================================================
__global__ __launch_bounds__(256) void gemm1_tc() {
    int e = blockIdx.z;
    int n = (e < NE) ? g_count[e] : T;
    int row0 = blockIdx.x * BM;
    if (row0 >= n) return;
    int j0 = blockIdx.y * 64;
    int tid = threadIdx.x;
    int lane = tid & 31;
    int wid = tid >> 5;
    int wm = wid & 3;            // M: 4 warps
    int wn = wid >> 2;           // N: 2 warps (32 cols each)

    extern __shared__ char smem[];
    uint32_t sb = s2u(smem);
    int* s_tok = (int*)(smem + SM_TOK);
    int* s_slot = (int*)(smem + SM_SLOT);

    if (tid < BM) {
        int pos = row0 + tid;
        int slot, tok;
        if (pos < n) {
            if (e < NE) { slot = g_elist[e * T + pos]; tok = slot >> 1; }
            else        { slot = ROWS_R + pos;         tok = pos; }
        } else {
            slot = -1;
            tok = (e < NE) ? (g_elist[e * T + row0] >> 1) : row0;
        }
        s_slot[tid] = slot;
        s_tok[tid] = tok;
    }
    __syncthreads();

    // ---- loader pointers: 2 uint4 per plane per thread ----
    int q0 = tid, q1 = tid + 256;
    int r0 = q0 >> 2, f0 = q0 & 3;
    int r1 = q1 >> 2, f1 = q1 & 3;
    uint32_t off0 = (uint32_t)(r0 * RSB + f0 * 16);
    uint32_t off1 = (uint32_t)(r1 * RSB + f1 * 16);
    const char* pAh0 = (const char*)(g_xh + (size_t)s_tok[r0] * HD) + f0 * 16;
    const char* pAl0 = (const char*)(g_xl + (size_t)s_tok[r0] * HD) + f0 * 16;
    const char* pAh1 = (const char*)(g_xh + (size_t)s_tok[r1] * HD) + f1 * 16;
    const char* pAl1 = (const char*)(g_xl + (size_t)s_tok[r1] * HD) + f1 * 16;
    size_t bo0 = (r0 < 64) ? ((size_t)e * ID + j0 + r0) * HD
                           : ((size_t)e * ID + j0 + r0 - 64) * HD;
    size_t bo1 = (r1 < 64) ? ((size_t)e * ID + j0 + r1) * HD
                           : ((size_t)e * ID + j0 + r1 - 64) * HD;
    const char* pBh0 = (const char*)((r0 < 64 ? g_wgh : g_wuh) + bo0) + f0 * 16;
    const char* pBl0 = (const char*)((r0 < 64 ? g_wgl : g_wul) + bo0) + f0 * 16;
    const char* pBh1 = (const char*)((r1 < 64 ? g_wgh : g_wuh) + bo1) + f1 * 16;
    const char* pBl1 = (const char*)((r1 < 64 ? g_wgl : g_wul) + bo1) + f1 * 16;

#define G1_LOAD(bb) do { \
    CPA16((bb) + off0, pAh0); CPA16((bb) + PL + off0, pAl0); \
    CPA16((bb) + off1, pAh1); CPA16((bb) + PL + off1, pAl1); \
    CPA16((bb) + 2 * PL + off0, pBh0); CPA16((bb) + 3 * PL + off0, pBl0); \
    CPA16((bb) + 2 * PL + off1, pBh1); CPA16((bb) + 3 * PL + off1, pBl1); \
    pAh0 += 64; pAl0 += 64; pAh1 += 64; pAl1 += 64; \
    pBh0 += 64; pBl0 += 64; pBh1 += 64; pBl1 += 64; \
    CP_COMMIT(); } while (0)

    float accg[2][4][4], accu[2][4][4];
#pragma unroll
    for (int mt = 0; mt < 2; mt++)
#pragma unroll
        for (int nt = 0; nt < 4; nt++)
#pragma unroll
            for (int c = 0; c < 4; c++) { accg[mt][nt][c] = 0.f; accu[mt][nt][c] = 0.f; }

    // per-lane ldmatrix address components
    int lr = lane & 7;
    int aro = ((lane >> 3) & 1) * 8 + lr;     // A row-in-16
    int akb = (lane >> 4) * 16;               // A k-byte half
    int bro = ((lane >> 4) & 1) * 8 + lr;     // B row-in-16
    int bkb = ((lane >> 3) & 1) * 16;         // B k-byte half

    uint32_t buf0 = sb + SM_BUF0;
    G1_LOAD(buf0);

    for (int c = 0; c < NC1; c++) {
        if (c + 1 < NC1) G1_LOAD(sb + SM_BUF0 + ((c + 1) & 1) * BUFB);
        else CP_COMMIT();
        CP_WAIT1();
        __syncthreads();
        uint32_t bb = sb + SM_BUF0 + (c & 1) * BUFB;

#pragma unroll
        for (int ks = 0; ks < 2; ks++) {
            int kb = ks * 32;
            uint32_t ah[2][4], al[2][4];
#pragma unroll
            for (int mt = 0; mt < 2; mt++) {
                uint32_t ra = bb + (uint32_t)((wm * 32 + mt * 16 + aro) * RSB) + kb + akb;
                ldsm4(ah[mt], ra);
                ldsm4(al[mt], ra + PL);
            }
            uint32_t bgh[4][2], bgl[4][2], buh[4][2], bul[4][2];
#pragma unroll
            for (int p = 0; p < 2; p++) {
                uint32_t rb = bb + 2 * PL + (uint32_t)((wn * 32 + p * 16 + bro) * RSB) + kb + bkb;
                uint32_t rg[4];
                ldsm4(rg, rb);
                bgh[2 * p][0] = rg[0]; bgh[2 * p][1] = rg[1];
                bgh[2 * p + 1][0] = rg[2]; bgh[2 * p + 1][1] = rg[3];
                ldsm4(rg, rb + PL);
                bgl[2 * p][0] = rg[0]; bgl[2 * p][1] = rg[1];
                bgl[2 * p + 1][0] = rg[2]; bgl[2 * p + 1][1] = rg[3];
                ldsm4(rg, rb + 64 * RSB);
                buh[2 * p][0] = rg[0]; buh[2 * p][1] = rg[1];
                buh[2 * p + 1][0] = rg[2]; buh[2 * p + 1][1] = rg[3];
                ldsm4(rg, rb + 64 * RSB + PL);
                bul[2 * p][0] = rg[0]; bul[2 * p][1] = rg[1];
                bul[2 * p + 1][0] = rg[2]; bul[2 * p + 1][1] = rg[3];
            }
#pragma unroll
            for (int mt = 0; mt < 2; mt++)
#pragma unroll
                for (int nt = 0; nt < 4; nt++) {
                    mma16816(accg[mt][nt], ah[mt], bgh[nt]);
                    mma16816(accg[mt][nt], ah[mt], bgl[nt]);
                    mma16816(accg[mt][nt], al[mt], bgh[nt]);
                    mma16816(accu[mt][nt], ah[mt], buh[nt]);
                    mma16816(accu[mt][nt], ah[mt], bul[nt]);
                    mma16816(accu[mt][nt], al[mt], buh[nt]);
                }
        }
        __syncthreads();
    }
#undef G1_LOAD

    // ---- epilogue: silu(gate)*up -> bf16 hi/lo ----
#pragma unroll
    for (int mt = 0; mt < 2; mt++) {
        int rA = wm * 32 + mt * 16 + (lane >> 2);
        int sl0 = s_slot[rA], sl1 = s_slot[rA + 8];
#pragma unroll
        for (int nt = 0; nt < 4; nt++) {
            int col = j0 + wn * 32 + nt * 8 + (lane & 3) * 2;
#pragma unroll
            for (int hhalf = 0; hhalf < 2; hhalf++) {
                int sl = hhalf ? sl1 : sl0;
                if (sl < 0) continue;
                float g0 = accg[mt][nt][hhalf * 2], g1 = accg[mt][nt][hhalf * 2 + 1];
                float u0 = accu[mt][nt][hhalf * 2], u1 = accu[mt][nt][hhalf * 2 + 1];
                float a0 = (g0 * u0) / (1.0f + __expf(-g0));
                float a1 = (g1 * u1) / (1.0f + __expf(-g1));
                __nv_bfloat16 h0 = __float2bfloat16(a0), h1 = __float2bfloat16(a1);
                __nv_bfloat162 hh, ll;
                hh.x = h0; hh.y = h1;
                ll.x = __float2bfloat16(a0 - __bfloat162float(h0));
                ll.y = __float2bfloat16(a1 - __bfloat162float(h1));
                size_t o = (size_t)sl * ID + col;
                *(__nv_bfloat162*)(g_acth + o) = hh;
                *(__nv_bfloat162*)(g_actl + o) = ll;
            }
        }
    }
}

// ============================================================
// GEMM2 (mma.sync bf16 3-term): per CTA 128 rows x 128 cols -> g_y fp32
// ============================================================
__global__ __launch_bounds__(256) void gemm2_tc() {
    int e = blockIdx.z;
    int n = (e < NE) ? g_count[e] : T;
    int row0 = blockIdx.x * BM;
    if (row0 >= n) return;
    int j0 = blockIdx.y * 128;
    int tid = threadIdx.x;
    int lane = tid & 31;
    int wid = tid >> 5;
    int wm = wid & 3;
    int wn = wid >> 2;           // 2 warps x 64 cols

    extern __shared__ char smem[];
    uint32_t sb = s2u(smem);
    int* s_arow = (int*)(smem + SM_TOK);
    int* s_slot = (int*)(smem + SM_SLOT);

    if (tid < BM) {
        int pos = row0 + tid;
        int slot;
        if (pos < n) slot = (e < NE) ? g_elist[e * T + pos] : (ROWS_R + pos);
        else         slot = -1;
        s_slot[tid] = slot;
        s_arow[tid] = (slot >= 0) ? slot
                                  : ((e < NE) ? g_elist[e * T + row0] : (ROWS_R + row0));
    }
    __syncthreads();

    int q0 = tid, q1 = tid + 256;
    int r0 = q0 >> 2, f0 = q0 & 3;
    int r1 = q1 >> 2, f1 = q1 & 3;
    uint32_t off0 = (uint32_t)(r0 * RSB + f0 * 16);
    uint32_t off1 = (uint32_t)(r1 * RSB + f1 * 16);
    const char* pAh0 = (const char*)(g_acth + (size_t)s_arow[r0] * ID) + f0 * 16;
    const char* pAl0 = (const char*)(g_actl + (size_t)s_arow[r0] * ID) + f0 * 16;
    const char* pAh1 = (const char*)(g_acth + (size_t)s_arow[r1] * ID) + f1 * 16;
    const char* pAl1 = (const char*)(g_actl + (size_t)s_arow[r1] * ID) + f1 * 16;
    size_t bo0 = ((size_t)e * HD + j0 + r0) * ID;
    size_t bo1 = ((size_t)e * HD + j0 + r1) * ID;
    const char* pBh0 = (const char*)(g_wdh + bo0) + f0 * 16;
    const char* pBl0 = (const char*)(g_wdl + bo0) + f0 * 16;
    const char* pBh1 = (const char*)(g_wdh + bo1) + f1 * 16;
    const char* pBl1 = (const char*)(g_wdl + bo1) + f1 * 16;

#define G2_LOAD(bb) do { \
    CPA16((bb) + off0, pAh0); CPA16((bb) + PL + off0, pAl0); \
    CPA16((bb) + off1, pAh1); CPA16((bb) + PL + off1, pAl1); \
    CPA16((bb) + 2 * PL + off0, pBh0); CPA16((bb) + 3 * PL + off0, pBl0); \
    CPA16((bb) + 2 * PL + off1, pBh1); CPA16((bb) + 3 * PL + off1, pBl1); \
    pAh0 += 64; pAl0 += 64; pAh1 += 64; pAl1 += 64; \
    pBh0 += 64; pBl0 += 64; pBh1 += 64; pBl1 += 64; \
    CP_COMMIT(); } while (0)

    float acc[2][8][4];
#pragma unroll
    for (int mt = 0; mt < 2; mt++)
#pragma unroll
        for (int nt = 0; nt < 8; nt++)
#pragma unroll
            for (int c = 0; c < 4; c++) acc[mt][nt][c] = 0.f;

    int lr = lane & 7;
    int aro = ((lane >> 3) & 1) * 8 + lr;
    int akb = (lane >> 4) * 16;
    int bro = ((lane >> 4) & 1) * 8 + lr;
    int bkb = ((lane >> 3) & 1) * 16;

    G2_LOAD(sb + SM_BUF0);

    for (int c = 0; c < NC2; c++) {
        if (c + 1 < NC2) G2_LOAD(sb + SM_BUF0 + ((c + 1) & 1) * BUFB);
        else CP_COMMIT();
        CP_WAIT1();
        __syncthreads();
        uint32_t bb = sb + SM_BUF0 + (c & 1) * BUFB;

#pragma unroll
        for (int ks = 0; ks < 2; ks++) {
            int kb = ks * 32;
            uint32_t ah[2][4], al[2][4];
#pragma unroll
            for (int mt = 0; mt < 2; mt++) {
                uint32_t ra = bb + (uint32_t)((wm * 32 + mt * 16 + aro) * RSB) + kb + akb;
                ldsm4(ah[mt], ra);
                ldsm4(al[mt], ra + PL);
            }
            uint32_t bh[8][2], bl[8][2];
#pragma unroll
            for (int p = 0; p < 4; p++) {
                uint32_t rb = bb + 2 * PL + (uint32_t)((wn * 64 + p * 16 + bro) * RSB) + kb + bkb;
                uint32_t rg[4];
                ldsm4(rg, rb);
                bh[2 * p][0] = rg[0]; bh[2 * p][1] = rg[1];
                bh[2 * p + 1][0] = rg[2]; bh[2 * p + 1][1] = rg[3];
                ldsm4(rg, rb + PL);
                bl[2 * p][0] = rg[0]; bl[2 * p][1] = rg[1];
                bl[2 * p + 1][0] = rg[2]; bl[2 * p + 1][1] = rg[3];
            }
#pragma unroll
            for (int mt = 0; mt < 2; mt++)
#pragma unroll
                for (int nt = 0; nt < 8; nt++) {
                    mma16816(acc[mt][nt], ah[mt], bh[nt]);
                    mma16816(acc[mt][nt], ah[mt], bl[nt]);
                    mma16816(acc[mt][nt], al[mt], bh[nt]);
                }
        }
        __syncthreads();
    }
#undef G2_LOAD

    // ---- epilogue: fp32 stores to g_y ----
#pragma unroll
    for (int mt = 0; mt < 2; mt++) {
        int rA = wm * 32 + mt * 16 + (lane >> 2);
        int sl0 = s_slot[rA], sl1 = s_slot[rA + 8];
#pragma unroll
        for (int nt = 0; nt < 8; nt++) {
            int col = j0 + wn * 64 + nt * 8 + (lane & 3) * 2;
            if (sl0 >= 0) {
                float2 v; v.x = acc[mt][nt][0]; v.y = acc[mt][nt][1];
                *(float2*)(g_y + (size_t)sl0 * HD + col) = v;
            }
            if (sl1 >= 0) {
                float2 v; v.x = acc[mt][nt][2]; v.y = acc[mt][nt][3];
                *(float2*)(g_y + (size_t)sl1 * HD + col) = v;
            }
        }
    }
}

// ============================================================
// combine: out[t] = w0*y[2t] + w1*y[2t+1] + y_shared[t]
// ============================================================
__global__ void combine_kernel(float* __restrict__ out) {
    int idx = blockIdx.x * blockDim.x + threadIdx.x;
    int t = idx / (HD / 4);
    int c = (idx % (HD / 4)) * 4;
    float w0 = g_wslot[2 * t];
    float w1 = g_wslot[2 * t + 1];
    float4 y0 = *(const float4*)(g_y + (size_t)(2 * t) * HD + c);
    float4 y1 = *(const float4*)(g_y + (size_t)(2 * t + 1) * HD + c);
    float4 ys = *(const float4*)(g_y + (size_t)(ROWS_R + t) * HD + c);
    float4 r;
    r.x = fmaf(w0, y0.x, fmaf(w1, y1.x, ys.x));
    r.y = fmaf(w0, y0.y, fmaf(w1, y1.y, ys.y));
    r.z = fmaf(w0, y0.z, fmaf(w1, y1.z, ys.z));
    r.w = fmaf(w0, y0.w, fmaf(w1, y1.w, ys.w));
    *(float4*)(out + (size_t)t * HD + c) = r;
}

// ============================================================
extern "C" void kernel_launch(void* const* d_in, const int* in_sizes, int n_in,
                              void* d_out, int out_size) {
    const float* x   = (const float*)d_in[0];
    const float* rw  = (const float*)d_in[1];
    const float* gw  = (const float*)d_in[2];
    const float* uw  = (const float*)d_in[3];
    const float* dw  = (const float*)d_in[4];
    const float* sgw = (const float*)d_in[5];
    const float* suw = (const float*)d_in[6];
    const float* sdw = (const float*)d_in[7];
    float* out = (float*)d_out;

    cudaFuncSetAttribute(gemm1_tc, cudaFuncAttributeMaxDynamicSharedMemorySize, SMEM_BYTES);
    cudaFuncSetAttribute(gemm2_tc, cudaFuncAttributeMaxDynamicSharedMemorySize, SMEM_BYTES);

    reset_kernel<<<1, 32>>>();
    convx_kernel<<<(T * HD / 4) / 256, 256>>>(x);
    convw_kernel<<<dim3(ID / 32, HD / 32, 9), dim3(32, 8)>>>(gw, sgw, 0, HD, ID);
    convw_kernel<<<dim3(ID / 32, HD / 32, 9), dim3(32, 8)>>>(uw, suw, 1, HD, ID);
    convw_kernel<<<dim3(HD / 32, ID / 32, 9), dim3(32, 8)>>>(dw, sdw, 2, ID, HD);
    router_kernel<<<T / 4, 128>>>(x, rw, out);
    finalize_kernel<<<1, 1>>>(out);
    gemm1_tc<<<dim3(T / BM, ID / 64, NE + 1), 256, SMEM_BYTES>>>();
    gemm2_tc<<<dim3(T / BM, HD / 128, NE + 1), 256, SMEM_BYTES>>>();
    combine_kernel<<<(T * HD / 4) / 256, 256>>>(out);
}

// round 8
// speedup vs baseline: 3.1966x; 1.5155x over previous
#include <cuda_runtime.h>
#include <cuda_fp16.h>
#include <math.h>
#include <cstdint>

#define T 4096
#define HD 1024
#define ID 2048
#define NE 8
#define NK 2
#define ROWS_R (T * NK)          /* 8192 routed rows (t*2+k) */
#define ROWS_ALL (ROWS_R + T)    /* + 4096 shared rows       */

#define OUT_AUX ((size_t)T * HD)
#define OUT_Z (OUT_AUX + 1)
#define OUT_LOGITS (OUT_Z + 1)

#define BM 128
#define BKC 32                   /* k-chunk (fp16 elems) = 64 bytes */
#define NC1 (HD / BKC)           /* 32 iters gemm1 */
#define NC2 (ID / BKC)           /* 64 iters gemm2 */
#define RSB 80                   /* smem row stride bytes (40 fp16) */

// smem plane: 128 rows * 80B = 10240; buffer = Ah | Al | B  (3 planes)
#define PL 10240
#define BUFB (3 * PL)            /* 30720 */
#define SM_TOK 0
#define SM_SLOT 512
#define SM_BUF0 1024
#define SMEM_BYTES (1024 + 2 * BUFB)   /* 62464 */

typedef unsigned long long u64;

// ---------------- device scratch (static; no allocs allowed) ----------------
__device__ __half g_wg[(size_t)9 * ID * HD];    // gate  [e][n][k] fp16
__device__ __half g_wu[(size_t)9 * ID * HD];    // up    [e][n][k] fp16
__device__ __half g_wd[(size_t)9 * HD * ID];    // down  [e][n][k] fp16
__device__ __half g_xh[(size_t)T * HD];
__device__ __half g_xl[(size_t)T * HD];
__device__ __half g_acth[(size_t)ROWS_ALL * ID];
__device__ __half g_actl[(size_t)ROWS_ALL * ID];
__device__ float g_y[(size_t)ROWS_ALL * HD];
__device__ int   g_elist[NE * T];
__device__ int   g_count[NE];
__device__ float g_wslot[T * NK];
__device__ float g_probsum[NE];
__device__ float g_zsum;

// ---------------- PTX helpers (plain sm_103-safe) ----------------
static __device__ __forceinline__ uint32_t s2u(const void* p) {
    uint32_t a;
    asm("{ .reg .u64 t; cvta.to.shared.u64 t, %1; cvt.u32.u64 %0, t; }"
        : "=r"(a) : "l"(p));
    return a;
}

#define CPA16(sa, ga) \
    asm volatile("cp.async.cg.shared.global [%0], [%1], 16;" \
        :: "r"((uint32_t)(sa)), "l"(ga) : "memory")
#define CP_COMMIT() asm volatile("cp.async.commit_group;" ::: "memory")
#define CP_WAIT1()  asm volatile("cp.async.wait_group 1;" ::: "memory")

static __device__ __forceinline__ void ldsm4(uint32_t* r, uint32_t a) {
    asm volatile("ldmatrix.sync.aligned.m8n8.x4.shared.b16 {%0,%1,%2,%3}, [%4];"
        : "=r"(r[0]), "=r"(r[1]), "=r"(r[2]), "=r"(r[3]) : "r"(a));
}

static __device__ __forceinline__ void mma16816(float* d, const uint32_t* a,
                                                const uint32_t* b) {
    asm volatile(
        "mma.sync.aligned.m16n8k16.row.col.f32.f16.f16.f32 "
        "{%0,%1,%2,%3}, {%4,%5,%6,%7}, {%8,%9}, {%0,%1,%2,%3};"
        : "+f"(d[0]), "+f"(d[1]), "+f"(d[2]), "+f"(d[3])
        : "r"(a[0]), "r"(a[1]), "r"(a[2]), "r"(a[3]), "r"(b[0]), "r"(b[1]));
}

// ============================================================
__global__ void reset_kernel() {
    int i = threadIdx.x;
    if (i < NE) { g_count[i] = 0; g_probsum[i] = 0.f; }
    if (i == 0) g_zsum = 0.f;
}

// ============================================================
// convert x -> fp16 hi/lo planes
// ============================================================
__global__ void convx_kernel(const float* __restrict__ x) {
    size_t i = ((size_t)blockIdx.x * blockDim.x + threadIdx.x) * 4;
    float4 v = *(const float4*)(x + i);
    __half h0 = __float2half_rn(v.x), h1 = __float2half_rn(v.y);
    __half h2 = __float2half_rn(v.z), h3 = __float2half_rn(v.w);
    __half2 p0, p1, q0, q1;
    p0.x = h0; p0.y = h1; p1.x = h2; p1.y = h3;
    q0.x = __float2half_rn(v.x - __half2float(h0));
    q0.y = __float2half_rn(v.y - __half2float(h1));
    q1.x = __float2half_rn(v.z - __half2float(h2));
    q1.y = __float2half_rn(v.w - __half2float(h3));
    *(__half2*)(g_xh + i) = p0;
    *(__half2*)(g_xh + i + 2) = p1;
    *(__half2*)(g_xl + i) = q0;
    *(__half2*)(g_xl + i + 2) = q1;
}

// ============================================================
// convert + transpose ALL weights in one launch:
// z in [0,27): mat = z/9 (0=gate,1=up,2=down), e = z%9
// src [K][N] fp32 -> dst [e][N][K] fp16 (hi only)
// ============================================================
__global__ void convw_kernel(const float* __restrict__ gw,
                             const float* __restrict__ uw,
                             const float* __restrict__ dw,
                             const float* __restrict__ sgw,
                             const float* __restrict__ suw,
                             const float* __restrict__ sdw) {
    int mat = blockIdx.z / 9;
    int e = blockIdx.z % 9;
    __half* dst;
    const float* src;
    int K, N, n0, k0;
    if (mat == 0) {
        dst = g_wg; src = (e < NE) ? gw + (size_t)e * HD * ID : sgw;
        K = HD; N = ID; n0 = blockIdx.x * 32; k0 = blockIdx.y * 32;
    } else if (mat == 1) {
        dst = g_wu; src = (e < NE) ? uw + (size_t)e * HD * ID : suw;
        K = HD; N = ID; n0 = blockIdx.x * 32; k0 = blockIdx.y * 32;
    } else {
        dst = g_wd; src = (e < NE) ? dw + (size_t)e * ID * HD : sdw;
        K = ID; N = HD; n0 = blockIdx.y * 32; k0 = blockIdx.x * 32;
    }
    __shared__ float tile[32][33];
    int tx = threadIdx.x;
    for (int i = threadIdx.y; i < 32; i += 8)
        tile[i][tx] = src[(size_t)(k0 + i) * N + n0 + tx];
    __syncthreads();
    size_t base = (size_t)e * K * N;
    for (int i = threadIdx.y; i < 32; i += 8)
        dst[base + (size_t)(n0 + i) * K + k0 + tx] = __float2half_rn(tile[tx][i]);
}

// ============================================================
// router: one warp per token
// ============================================================
__global__ void router_kernel(const float* __restrict__ x,
                              const float* __restrict__ rw,
                              float* __restrict__ out) {
    int warp = threadIdx.x >> 5;
    int lane = threadIdx.x & 31;
    int t = blockIdx.x * 4 + warp;
    if (t >= T) return;

    const float* xr = x + (size_t)t * HD;
    float acc[NE];
#pragma unroll
    for (int e = 0; e < NE; e++) acc[e] = 0.f;
    for (int h = lane; h < HD; h += 32) {
        float xv = xr[h];
        const float* r = rw + h * NE;
#pragma unroll
        for (int e = 0; e < NE; e++) acc[e] = fmaf(xv, r[e], acc[e]);
    }
#pragma unroll
    for (int off = 16; off; off >>= 1) {
#pragma unroll
        for (int e = 0; e < NE; e++)
            acc[e] += __shfl_xor_sync(0xffffffffu, acc[e], off);
    }

    if (lane == 0) {
        float m = acc[0];
#pragma unroll
        for (int e = 1; e < NE; e++) m = fmaxf(m, acc[e]);
        float s = 0.f;
#pragma unroll
        for (int e = 0; e < NE; e++) s += expf(acc[e] - m);
        float lse = m + logf(s);
        float p[NE];
#pragma unroll
        for (int e = 0; e < NE; e++) p[e] = expf(acc[e] - lse);

        int i0 = 0;
#pragma unroll
        for (int e = 1; e < NE; e++) if (p[e] > p[i0]) i0 = e;
        int i1 = (i0 == 0) ? 1 : 0;
#pragma unroll
        for (int e = 0; e < NE; e++) if (e != i1 && e != i0 && p[e] > p[i1]) i1 = e;

        float sum2 = p[i0] + p[i1];
        g_wslot[2 * t]     = p[i0] / sum2;
        g_wslot[2 * t + 1] = p[i1] / sum2;

        int pos0 = atomicAdd(&g_count[i0], 1);
        g_elist[i0 * T + pos0] = 2 * t;
        int pos1 = atomicAdd(&g_count[i1], 1);
        g_elist[i1 * T + pos1] = 2 * t + 1;

#pragma unroll
        for (int e = 0; e < NE; e++) {
            out[OUT_LOGITS + (size_t)t * NE + e] = acc[e];
            atomicAdd(&g_probsum[e], p[e]);
        }
        atomicAdd(&g_zsum, lse * lse);
    }
}

__global__ void finalize_kernel(float* __restrict__ out) {
    if (threadIdx.x == 0) {
        float aux = 0.f;
#pragma unroll
        for (int e = 0; e < NE; e++)
            aux += ((float)g_count[e] / (2.0f * (float)T)) * (g_probsum[e] / (float)T);
        out[OUT_AUX] = (float)NE * aux;
        out[OUT_Z] = g_zsum / (float)T;
    }
}

// ============================================================
// GEMM1 (mma.sync fp16 2-term split): per CTA 128 rows x 64 cols of
// BOTH gate and up; fused SiLU epilogue -> g_acth/g_actl (fp16 hi/lo).
// smem buffer: Ah | Al | B(gate rows 0-63, up rows 64-127)
// ============================================================
__global__ __launch_bounds__(256) void gemm1_tc() {
    int e = blockIdx.z;
    int n = (e < NE) ? g_count[e] : T;
    int row0 = blockIdx.x * BM;
    if (row0 >= n) return;
    int j0 = blockIdx.y * 64;
    int tid = threadIdx.x;
    int lane = tid & 31;
    int wid = tid >> 5;
    int wm = wid & 3;            // M: 4 warps
    int wn = wid >> 2;           // N: 2 warps (32 cols each)

    extern __shared__ char smem[];
    uint32_t sb = s2u(smem);
    int* s_tok = (int*)(smem + SM_TOK);
    int* s_slot = (int*)(smem + SM_SLOT);

    if (tid < BM) {
        int pos = row0 + tid;
        int slot, tok;
        if (pos < n) {
            if (e < NE) { slot = g_elist[e * T + pos]; tok = slot >> 1; }
            else        { slot = ROWS_R + pos;         tok = pos; }
        } else {
            slot = -1;
            tok = (e < NE) ? (g_elist[e * T + row0] >> 1) : row0;
        }
        s_slot[tid] = slot;
        s_tok[tid] = tok;
    }
    __syncthreads();

    // loaders: 6 x 16B per thread per chunk
    int q0 = tid, q1 = tid + 256;
    int r0 = q0 >> 2, f0 = q0 & 3;
    int r1 = q1 >> 2, f1 = q1 & 3;
    uint32_t off0 = (uint32_t)(r0 * RSB + f0 * 16);
    uint32_t off1 = (uint32_t)(r1 * RSB + f1 * 16);
    const char* pAh0 = (const char*)(g_xh + (size_t)s_tok[r0] * HD) + f0 * 16;
    const char* pAl0 = (const char*)(g_xl + (size_t)s_tok[r0] * HD) + f0 * 16;
    const char* pAh1 = (const char*)(g_xh + (size_t)s_tok[r1] * HD) + f1 * 16;
    const char* pAl1 = (const char*)(g_xl + (size_t)s_tok[r1] * HD) + f1 * 16;
    // B plane rows: r0 (0-63) -> gate row j0+r0 ; r1 (64-127) -> up row j0+r1-64
    const char* pB0 = (const char*)(g_wg + ((size_t)e * ID + j0 + r0) * HD) + f0 * 16;
    const char* pB1 = (const char*)(g_wu + ((size_t)e * ID + j0 + r1 - 64) * HD) + f1 * 16;

#define G1_LOAD(bb) do { \
    CPA16((bb) + off0, pAh0); CPA16((bb) + PL + off0, pAl0); \
    CPA16((bb) + off1, pAh1); CPA16((bb) + PL + off1, pAl1); \
    CPA16((bb) + 2 * PL + off0, pB0); CPA16((bb) + 2 * PL + off1, pB1); \
    pAh0 += 64; pAl0 += 64; pAh1 += 64; pAl1 += 64; \
    pB0 += 64; pB1 += 64; \
    CP_COMMIT(); } while (0)

    float accg[2][4][4], accu[2][4][4];
#pragma unroll
    for (int mt = 0; mt < 2; mt++)
#pragma unroll
        for (int nt = 0; nt < 4; nt++)
#pragma unroll
            for (int c = 0; c < 4; c++) { accg[mt][nt][c] = 0.f; accu[mt][nt][c] = 0.f; }

    int lr = lane & 7;
    int aro = ((lane >> 3) & 1) * 8 + lr;     // A row-in-16
    int akb = (lane >> 4) * 16;               // A k-byte half
    int bro = ((lane >> 4) & 1) * 8 + lr;     // B row-in-16
    int bkb = ((lane >> 3) & 1) * 16;         // B k-byte half

    G1_LOAD(sb + SM_BUF0);

    for (int c = 0; c < NC1; c++) {
        if (c + 1 < NC1) G1_LOAD(sb + SM_BUF0 + ((c + 1) & 1) * BUFB);
        else CP_COMMIT();
        CP_WAIT1();
        __syncthreads();
        uint32_t bb = sb + SM_BUF0 + (c & 1) * BUFB;

#pragma unroll
        for (int ks = 0; ks < 2; ks++) {
            int kb = ks * 32;
            uint32_t ah[2][4], al[2][4];
#pragma unroll
            for (int mt = 0; mt < 2; mt++) {
                uint32_t ra = bb + (uint32_t)((wm * 32 + mt * 16 + aro) * RSB) + kb + akb;
                ldsm4(ah[mt], ra);
                ldsm4(al[mt], ra + PL);
            }
            uint32_t bg[4][2], bu[4][2];
#pragma unroll
            for (int p = 0; p < 2; p++) {
                uint32_t rb = bb + 2 * PL + (uint32_t)((wn * 32 + p * 16 + bro) * RSB) + kb + bkb;
                uint32_t rg[4];
                ldsm4(rg, rb);
                bg[2 * p][0] = rg[0]; bg[2 * p][1] = rg[1];
                bg[2 * p + 1][0] = rg[2]; bg[2 * p + 1][1] = rg[3];
                ldsm4(rg, rb + 64 * RSB);
                bu[2 * p][0] = rg[0]; bu[2 * p][1] = rg[1];
                bu[2 * p + 1][0] = rg[2]; bu[2 * p + 1][1] = rg[3];
            }
#pragma unroll
            for (int mt = 0; mt < 2; mt++)
#pragma unroll
                for (int nt = 0; nt < 4; nt++) {
                    mma16816(accg[mt][nt], ah[mt], bg[nt]);
                    mma16816(accg[mt][nt], al[mt], bg[nt]);
                    mma16816(accu[mt][nt], ah[mt], bu[nt]);
                    mma16816(accu[mt][nt], al[mt], bu[nt]);
                }
        }
        __syncthreads();
    }
#undef G1_LOAD

    // ---- epilogue: silu(gate)*up -> fp16 hi/lo ----
#pragma unroll
    for (int mt = 0; mt < 2; mt++) {
        int rA = wm * 32 + mt * 16 + (lane >> 2);
        int sl0 = s_slot[rA], sl1 = s_slot[rA + 8];
#pragma unroll
        for (int nt = 0; nt < 4; nt++) {
            int col = j0 + wn * 32 + nt * 8 + (lane & 3) * 2;
#pragma unroll
            for (int hhalf = 0; hhalf < 2; hhalf++) {
                int sl = hhalf ? sl1 : sl0;
                if (sl < 0) continue;
                float g0 = accg[mt][nt][hhalf * 2], g1 = accg[mt][nt][hhalf * 2 + 1];
                float u0 = accu[mt][nt][hhalf * 2], u1 = accu[mt][nt][hhalf * 2 + 1];
                float a0 = (g0 * u0) / (1.0f + __expf(-g0));
                float a1 = (g1 * u1) / (1.0f + __expf(-g1));
                __half h0 = __float2half_rn(a0), h1 = __float2half_rn(a1);
                __half2 hh, ll;
                hh.x = h0; hh.y = h1;
                ll.x = __float2half_rn(a0 - __half2float(h0));
                ll.y = __float2half_rn(a1 - __half2float(h1));
                size_t o = (size_t)sl * ID + col;
                *(__half2*)(g_acth + o) = hh;
                *(__half2*)(g_actl + o) = ll;
            }
        }
    }
}

// ============================================================
// GEMM2 (mma.sync fp16 2-term): per CTA 128 rows x 128 cols -> g_y fp32
// ============================================================
__global__ __launch_bounds__(256) void gemm2_tc() {
    int e = blockIdx.z;
    int n = (e < NE) ? g_count[e] : T;
    int row0 = blockIdx.x * BM;
    if (row0 >= n) return;
    int j0 = blockIdx.y * 128;
    int tid = threadIdx.x;
    int lane = tid & 31;
    int wid = tid >> 5;
    int wm = wid & 3;
    int wn = wid >> 2;           // 2 warps x 64 cols

    extern __shared__ char smem[];
    uint32_t sb = s2u(smem);
    int* s_arow = (int*)(smem + SM_TOK);
    int* s_slot = (int*)(smem + SM_SLOT);

    if (tid < BM) {
        int pos = row0 + tid;
        int slot;
        if (pos < n) slot = (e < NE) ? g_elist[e * T + pos] : (ROWS_R + pos);
        else         slot = -1;
        s_slot[tid] = slot;
        s_arow[tid] = (slot >= 0) ? slot
                                  : ((e < NE) ? g_elist[e * T + row0] : (ROWS_R + row0));
    }
    __syncthreads();

    int q0 = tid, q1 = tid + 256;
    int r0 = q0 >> 2, f0 = q0 & 3;
    int r1 = q1 >> 2, f1 = q1 & 3;
    uint32_t off0 = (uint32_t)(r0 * RSB + f0 * 16);
    uint32_t off1 = (uint32_t)(r1 * RSB + f1 * 16);
    const char* pAh0 = (const char*)(g_acth + (size_t)s_arow[r0] * ID) + f0 * 16;
    const char* pAl0 = (const char*)(g_actl + (size_t)s_arow[r0] * ID) + f0 * 16;
    const char* pAh1 = (const char*)(g_acth + (size_t)s_arow[r1] * ID) + f1 * 16;
    const char* pAl1 = (const char*)(g_actl + (size_t)s_arow[r1] * ID) + f1 * 16;
    const char* pB0 = (const char*)(g_wd + ((size_t)e * HD + j0 + r0) * ID) + f0 * 16;
    const char* pB1 = (const char*)(g_wd + ((size_t)e * HD + j0 + r1) * ID) + f1 * 16;

#define G2_LOAD(bb) do { \
    CPA16((bb) + off0, pAh0); CPA16((bb) + PL + off0, pAl0); \
    CPA16((bb) + off1, pAh1); CPA16((bb) + PL + off1, pAl1); \
    CPA16((bb) + 2 * PL + off0, pB0); CPA16((bb) + 2 * PL + off1, pB1); \
    pAh0 += 64; pAl0 += 64; pAh1 += 64; pAl1 += 64; \
    pB0 += 64; pB1 += 64; \
    CP_COMMIT(); } while (0)

    float acc[2][8][4];
#pragma unroll
    for (int mt = 0; mt < 2; mt++)
#pragma unroll
        for (int nt = 0; nt < 8; nt++)
#pragma unroll
            for (int c = 0; c < 4; c++) acc[mt][nt][c] = 0.f;

    int lr = lane & 7;
    int aro = ((lane >> 3) & 1) * 8 + lr;
    int akb = (lane >> 4) * 16;
    int bro = ((lane >> 4) & 1) * 8 + lr;
    int bkb = ((lane >> 3) & 1) * 16;

    G2_LOAD(sb + SM_BUF0);

    for (int c = 0; c < NC2; c++) {
        if (c + 1 < NC2) G2_LOAD(sb + SM_BUF0 + ((c + 1) & 1) * BUFB);
        else CP_COMMIT();
        CP_WAIT1();
        __syncthreads();
        uint32_t bb = sb + SM_BUF0 + (c & 1) * BUFB;

#pragma unroll
        for (int ks = 0; ks < 2; ks++) {
            int kb = ks * 32;
            uint32_t ah[2][4], al[2][4];
#pragma unroll
            for (int mt = 0; mt < 2; mt++) {
                uint32_t ra = bb + (uint32_t)((wm * 32 + mt * 16 + aro) * RSB) + kb + akb;
                ldsm4(ah[mt], ra);
                ldsm4(al[mt], ra + PL);
            }
            uint32_t bh[8][2];
#pragma unroll
            for (int p = 0; p < 4; p++) {
                uint32_t rb = bb + 2 * PL + (uint32_t)((wn * 64 + p * 16 + bro) * RSB) + kb + bkb;
                uint32_t rg[4];
                ldsm4(rg, rb);
                bh[2 * p][0] = rg[0]; bh[2 * p][1] = rg[1];
                bh[2 * p + 1][0] = rg[2]; bh[2 * p + 1][1] = rg[3];
            }
#pragma unroll
            for (int mt = 0; mt < 2; mt++)
#pragma unroll
                for (int nt = 0; nt < 8; nt++) {
                    mma16816(acc[mt][nt], ah[mt], bh[nt]);
                    mma16816(acc[mt][nt], al[mt], bh[nt]);
                }
        }
        __syncthreads();
    }
#undef G2_LOAD

    // ---- epilogue: fp32 stores to g_y ----
#pragma unroll
    for (int mt = 0; mt < 2; mt++) {
        int rA = wm * 32 + mt * 16 + (lane >> 2);
        int sl0 = s_slot[rA], sl1 = s_slot[rA + 8];
#pragma unroll
        for (int nt = 0; nt < 8; nt++) {
            int col = j0 + wn * 64 + nt * 8 + (lane & 3) * 2;
            if (sl0 >= 0) {
                float2 v; v.x = acc[mt][nt][0]; v.y = acc[mt][nt][1];
                *(float2*)(g_y + (size_t)sl0 * HD + col) = v;
            }
            if (sl1 >= 0) {
                float2 v; v.x = acc[mt][nt][2]; v.y = acc[mt][nt][3];
                *(float2*)(g_y + (size_t)sl1 * HD + col) = v;
            }
        }
    }
}

// ============================================================
// combine: out[t] = w0*y[2t] + w1*y[2t+1] + y_shared[t]
// ============================================================
__global__ void combine_kernel(float* __restrict__ out) {
    int idx = blockIdx.x * blockDim.x + threadIdx.x;
    int t = idx / (HD / 4);
    int c = (idx % (HD / 4)) * 4;
    float w0 = g_wslot[2 * t];
    float w1 = g_wslot[2 * t + 1];
    float4 y0 = *(const float4*)(g_y + (size_t)(2 * t) * HD + c);
    float4 y1 = *(const float4*)(g_y + (size_t)(2 * t + 1) * HD + c);
    float4 ys = *(const float4*)(g_y + (size_t)(ROWS_R + t) * HD + c);
    float4 r;
    r.x = fmaf(w0, y0.x, fmaf(w1, y1.x, ys.x));
    r.y = fmaf(w0, y0.y, fmaf(w1, y1.y, ys.y));
    r.z = fmaf(w0, y0.z, fmaf(w1, y1.z, ys.z));
    r.w = fmaf(w0, y0.w, fmaf(w1, y1.w, ys.w));
    *(float4*)(out + (size_t)t * HD + c) = r;
}

// ============================================================
extern "C" void kernel_launch(void* const* d_in, const int* in_sizes, int n_in,
                              void* d_out, int out_size) {
    const float* x   = (const float*)d_in[0];
    const float* rw  = (const float*)d_in[1];
    const float* gw  = (const float*)d_in[2];
    const float* uw  = (const float*)d_in[3];
    const float* dw  = (const float*)d_in[4];
    const float* sgw = (const float*)d_in[5];
    const float* suw = (const float*)d_in[6];
    const float* sdw = (const float*)d_in[7];
    float* out = (float*)d_out;

    cudaFuncSetAttribute(gemm1_tc, cudaFuncAttributeMaxDynamicSharedMemorySize, SMEM_BYTES);
    cudaFuncSetAttribute(gemm2_tc, cudaFuncAttributeMaxDynamicSharedMemorySize, SMEM_BYTES);

    reset_kernel<<<1, 32>>>();
    convx_kernel<<<(T * HD / 4) / 256, 256>>>(x);
    convw_kernel<<<dim3(64, 32, 27), dim3(32, 8)>>>(gw, uw, dw, sgw, suw, sdw);
    router_kernel<<<T / 4, 128>>>(x, rw, out);
    finalize_kernel<<<1, 1>>>(out);
    gemm1_tc<<<dim3(T / BM, ID / 64, NE + 1), 256, SMEM_BYTES>>>();
    gemm2_tc<<<dim3(T / BM, HD / 128, NE + 1), 256, SMEM_BYTES>>>();
    combine_kernel<<<(T * HD / 4) / 256, 256>>>(out);
}

// round 10
// speedup vs baseline: 4.4846x; 1.4029x over previous
#include <cuda_runtime.h>
#include <cuda_fp16.h>
#include <math.h>
#include <cstdint>

#define T 4096
#define HD 1024
#define ID 2048
#define NE 8
#define NK 2
#define ROWS_R (T * NK)          /* 8192 routed rows (t*2+k) */
#define ROWS_ALL (ROWS_R + T)    /* + 4096 shared rows       */

#define OUT_AUX ((size_t)T * HD)
#define OUT_Z (OUT_AUX + 1)
#define OUT_LOGITS (OUT_Z + 1)

#define BM 128
#define BKC 32                   /* k-chunk (fp16 elems) = 64 bytes */
#define NC1 (HD / BKC)           /* 32 iters gemm1 */
#define NC2 (ID / BKC)           /* 64 iters gemm2 */
#define RSB 80                   /* smem row stride bytes (40 fp16) */

// smem plane: 128 rows * 80B = 10240; buffer = A | B  (2 planes)
#define PL 10240
#define BUFB (2 * PL)            /* 20480 */
#define SM_TOK 0
#define SM_SLOT 512
#define SM_BUF0 1024
#define SMEM_BYTES (1024 + 2 * BUFB)   /* 41984 */

typedef unsigned long long u64;

// ---------------- device scratch (static; no allocs allowed) ----------------
__device__ __half g_wg[(size_t)9 * ID * HD];    // gate  [e][n][k] fp16
__device__ __half g_wu[(size_t)9 * ID * HD];    // up    [e][n][k] fp16
__device__ __half g_wd[(size_t)9 * HD * ID];    // down  [e][n][k] fp16
__device__ __half g_x[(size_t)T * HD];          // x fp16
__device__ __half g_act[(size_t)ROWS_ALL * ID]; // silu(gate)*up fp16
__device__ float g_y[(size_t)ROWS_ALL * HD];
__device__ int   g_elist[NE * T];
__device__ int   g_count[NE];
__device__ float g_wslot[T * NK];
__device__ float g_probsum[NE];
__device__ float g_zsum;

// ---------------- PTX helpers (plain sm_103-safe) ----------------
static __device__ __forceinline__ uint32_t s2u(const void* p) {
    uint32_t a;
    asm("{ .reg .u64 t; cvta.to.shared.u64 t, %1; cvt.u32.u64 %0, t; }"
        : "=r"(a) : "l"(p));
    return a;
}

#define CPA16(sa, ga) \
    asm volatile("cp.async.cg.shared.global [%0], [%1], 16;" \
        :: "r"((uint32_t)(sa)), "l"(ga) : "memory")
#define CP_COMMIT() asm volatile("cp.async.commit_group;" ::: "memory")
#define CP_WAIT1()  asm volatile("cp.async.wait_group 1;" ::: "memory")

static __device__ __forceinline__ void ldsm4(uint32_t* r, uint32_t a) {
    asm volatile("ldmatrix.sync.aligned.m8n8.x4.shared.b16 {%0,%1,%2,%3}, [%4];"
        : "=r"(r[0]), "=r"(r[1]), "=r"(r[2]), "=r"(r[3]) : "r"(a));
}

static __device__ __forceinline__ void mma16816(float* d, const uint32_t* a,
                                                const uint32_t* b) {
    asm volatile(
        "mma.sync.aligned.m16n8k16.row.col.f32.f16.f16.f32 "
        "{%0,%1,%2,%3}, {%4,%5,%6,%7}, {%8,%9}, {%0,%1,%2,%3};"
        : "+f"(d[0]), "+f"(d[1]), "+f"(d[2]), "+f"(d[3])
        : "r"(a[0]), "r"(a[1]), "r"(a[2]), "r"(a[3]), "r"(b[0]), "r"(b[1]));
}

// ============================================================
__global__ void reset_kernel() {
    int i = threadIdx.x;
    if (i < NE) { g_count[i] = 0; g_probsum[i] = 0.f; }
    if (i == 0) g_zsum = 0.f;
}

// ============================================================
// convert x -> fp16
// ============================================================
__global__ void convx_kernel(const float* __restrict__ x) {
    size_t i = ((size_t)blockIdx.x * blockDim.x + threadIdx.x) * 4;
    float4 v = *(const float4*)(x + i);
    __half2 p0, p1;
    p0.x = __float2half_rn(v.x); p0.y = __float2half_rn(v.y);
    p1.x = __float2half_rn(v.z); p1.y = __float2half_rn(v.w);
    *(__half2*)(g_x + i) = p0;
    *(__half2*)(g_x + i + 2) = p1;
}

// ============================================================
// convert + transpose ALL weights in one launch:
// z in [0,27): mat = z/9 (0=gate,1=up,2=down), e = z%9
// src [K][N] fp32 -> dst [e][N][K] fp16
// ============================================================
__global__ void convw_kernel(const float* __restrict__ gw,
                             const float* __restrict__ uw,
                             const float* __restrict__ dw,
                             const float* __restrict__ sgw,
                             const float* __restrict__ suw,
                             const float* __restrict__ sdw) {
    int mat = blockIdx.z / 9;
    int e = blockIdx.z % 9;
    __half* dst;
    const float* src;
    int K, N, n0, k0;
    if (mat == 0) {
        dst = g_wg; src = (e < NE) ? gw + (size_t)e * HD * ID : sgw;
        K = HD; N = ID; n0 = blockIdx.x * 32; k0 = blockIdx.y * 32;
    } else if (mat == 1) {
        dst = g_wu; src = (e < NE) ? uw + (size_t)e * HD * ID : suw;
        K = HD; N = ID; n0 = blockIdx.x * 32; k0 = blockIdx.y * 32;
    } else {
        dst = g_wd; src = (e < NE) ? dw + (size_t)e * ID * HD : sdw;
        K = ID; N = HD; n0 = blockIdx.y * 32; k0 = blockIdx.x * 32;
    }
    __shared__ float tile[32][33];
    int tx = threadIdx.x;
    for (int i = threadIdx.y; i < 32; i += 8)
        tile[i][tx] = src[(size_t)(k0 + i) * N + n0 + tx];
    __syncthreads();
    size_t base = (size_t)e * K * N;
    for (int i = threadIdx.y; i < 32; i += 8)
        dst[base + (size_t)(n0 + i) * K + k0 + tx] = __float2half_rn(tile[tx][i]);
}

// ============================================================
// router: 8 warps/block, one token per warp, float4 x loads.
// probsum/zsum aggregated in smem before global atomics.
// ============================================================
__global__ void router_kernel(const float* __restrict__ x,
                              const float* __restrict__ rw,
                              float* __restrict__ out) {
    int tid = threadIdx.x;
    int warp = tid >> 5;
    int lane = tid & 31;
    int t = blockIdx.x * 8 + warp;

    __shared__ float sp[NE];
    __shared__ float sz;
    if (tid < NE) sp[tid] = 0.f;
    if (tid == NE) sz = 0.f;
    __syncthreads();

    const float4* xr = (const float4*)(x + (size_t)t * HD);
    float acc[NE];
#pragma unroll
    for (int e = 0; e < NE; e++) acc[e] = 0.f;
#pragma unroll
    for (int i = 0; i < 8; i++) {
        int idx = lane + i * 32;             // float4 index 0..255
        float4 v = xr[idx];
        const float* r = rw + idx * 32;      // 4 consecutive rw rows
#pragma unroll
        for (int e = 0; e < NE; e++)
            acc[e] = fmaf(v.x, r[e],
                     fmaf(v.y, r[8 + e],
                     fmaf(v.z, r[16 + e],
                     fmaf(v.w, r[24 + e], acc[e]))));
    }
#pragma unroll
    for (int off = 16; off; off >>= 1) {
#pragma unroll
        for (int e = 0; e < NE; e++)
            acc[e] += __shfl_xor_sync(0xffffffffu, acc[e], off);
    }

    if (lane == 0) {
        float m = acc[0];
#pragma unroll
        for (int e = 1; e < NE; e++) m = fmaxf(m, acc[e]);
        float s = 0.f;
#pragma unroll
        for (int e = 0; e < NE; e++) s += expf(acc[e] - m);
        float lse = m + logf(s);
        float p[NE];
#pragma unroll
        for (int e = 0; e < NE; e++) p[e] = expf(acc[e] - lse);

        int i0 = 0;
#pragma unroll
        for (int e = 1; e < NE; e++) if (p[e] > p[i0]) i0 = e;
        int i1 = (i0 == 0) ? 1 : 0;
#pragma unroll
        for (int e = 0; e < NE; e++) if (e != i1 && e != i0 && p[e] > p[i1]) i1 = e;

        float sum2 = p[i0] + p[i1];
        g_wslot[2 * t]     = p[i0] / sum2;
        g_wslot[2 * t + 1] = p[i1] / sum2;

        int pos0 = atomicAdd(&g_count[i0], 1);
        g_elist[i0 * T + pos0] = 2 * t;
        int pos1 = atomicAdd(&g_count[i1], 1);
        g_elist[i1 * T + pos1] = 2 * t + 1;

#pragma unroll
        for (int e = 0; e < NE; e++) {
            out[OUT_LOGITS + (size_t)t * NE + e] = acc[e];
            atomicAdd(&sp[e], p[e]);
        }
        atomicAdd(&sz, lse * lse);
    }
    __syncthreads();
    if (tid < NE) atomicAdd(&g_probsum[tid], sp[tid]);
    if (tid == NE) atomicAdd(&g_zsum, sz);
}

__global__ void finalize_kernel(float* __restrict__ out) {
    if (threadIdx.x == 0) {
        float aux = 0.f;
#pragma unroll
        for (int e = 0; e < NE; e++)
            aux += ((float)g_count[e] / (2.0f * (float)T)) * (g_probsum[e] / (float)T);
        out[OUT_AUX] = (float)NE * aux;
        out[OUT_Z] = g_zsum / (float)T;
    }
}

// ============================================================
// GEMM1 (mma.sync fp16, single term): per CTA 128 rows x 64 cols of
// BOTH gate and up; fused SiLU epilogue -> g_act fp16.
// smem buffer: A | B(gate rows 0-63, up rows 64-127)
// ============================================================
__global__ __launch_bounds__(256) void gemm1_tc() {
    int e = blockIdx.z;
    int n = (e < NE) ? g_count[e] : T;
    int row0 = blockIdx.x * BM;
    if (row0 >= n) return;
    int j0 = blockIdx.y * 64;
    int tid = threadIdx.x;
    int lane = tid & 31;
    int wid = tid >> 5;
    int wm = wid & 3;            // M: 4 warps
    int wn = wid >> 2;           // N: 2 warps (32 cols each)

    extern __shared__ char smem[];
    uint32_t sb = s2u(smem);
    int* s_tok = (int*)(smem + SM_TOK);
    int* s_slot = (int*)(smem + SM_SLOT);

    if (tid < BM) {
        int pos = row0 + tid;
        int slot, tok;
        if (pos < n) {
            if (e < NE) { slot = g_elist[e * T + pos]; tok = slot >> 1; }
            else        { slot = ROWS_R + pos;         tok = pos; }
        } else {
            slot = -1;
            tok = (e < NE) ? (g_elist[e * T + row0] >> 1) : row0;
        }
        s_slot[tid] = slot;
        s_tok[tid] = tok;
    }
    __syncthreads();

    // loaders: 4 x 16B per thread per chunk (A: 2, B: 2)
    int r0 = tid >> 2, f0 = tid & 3;
    int r1 = r0 + 64, f1 = f0;
    uint32_t off0 = (uint32_t)(r0 * RSB + f0 * 16);
    uint32_t off1 = (uint32_t)(r1 * RSB + f1 * 16);
    const char* pA0 = (const char*)(g_x + (size_t)s_tok[r0] * HD) + f0 * 16;
    const char* pA1 = (const char*)(g_x + (size_t)s_tok[r1] * HD) + f1 * 16;
    // B plane rows: r0 (0-63) -> gate row j0+r0 ; r1 (64-127) -> up row j0+r1-64
    const char* pB0 = (const char*)(g_wg + ((size_t)e * ID + j0 + r0) * HD) + f0 * 16;
    const char* pB1 = (const char*)(g_wu + ((size_t)e * ID + j0 + r1 - 64) * HD) + f1 * 16;

#define G1_LOAD(bb) do { \
    CPA16((bb) + off0, pA0); CPA16((bb) + off1, pA1); \
    CPA16((bb) + PL + off0, pB0); CPA16((bb) + PL + off1, pB1); \
    pA0 += 64; pA1 += 64; pB0 += 64; pB1 += 64; \
    CP_COMMIT(); } while (0)

    float accg[2][4][4], accu[2][4][4];
#pragma unroll
    for (int mt = 0; mt < 2; mt++)
#pragma unroll
        for (int nt = 0; nt < 4; nt++)
#pragma unroll
            for (int c = 0; c < 4; c++) { accg[mt][nt][c] = 0.f; accu[mt][nt][c] = 0.f; }

    int lr = lane & 7;
    int aro = ((lane >> 3) & 1) * 8 + lr;     // A row-in-16
    int akb = (lane >> 4) * 16;               // A k-byte half
    int bro = ((lane >> 4) & 1) * 8 + lr;     // B row-in-16
    int bkb = ((lane >> 3) & 1) * 16;         // B k-byte half

    G1_LOAD(sb + SM_BUF0);

    for (int c = 0; c < NC1; c++) {
        if (c + 1 < NC1) G1_LOAD(sb + SM_BUF0 + ((c + 1) & 1) * BUFB);
        else CP_COMMIT();
        CP_WAIT1();
        __syncthreads();
        uint32_t bb = sb + SM_BUF0 + (c & 1) * BUFB;

#pragma unroll
        for (int ks = 0; ks < 2; ks++) {
            int kb = ks * 32;
            uint32_t ah[2][4];
#pragma unroll
            for (int mt = 0; mt < 2; mt++) {
                uint32_t ra = bb + (uint32_t)((wm * 32 + mt * 16 + aro) * RSB) + kb + akb;
                ldsm4(ah[mt], ra);
            }
            uint32_t bg[4][2], bu[4][2];
#pragma unroll
            for (int p = 0; p < 2; p++) {
                uint32_t rb = bb + PL + (uint32_t)((wn * 32 + p * 16 + bro) * RSB) + kb + bkb;
                uint32_t rg[4];
                ldsm4(rg, rb);
                bg[2 * p][0] = rg[0]; bg[2 * p][1] = rg[1];
                bg[2 * p + 1][0] = rg[2]; bg[2 * p + 1][1] = rg[3];
                ldsm4(rg, rb + 64 * RSB);
                bu[2 * p][0] = rg[0]; bu[2 * p][1] = rg[1];
                bu[2 * p + 1][0] = rg[2]; bu[2 * p + 1][1] = rg[3];
            }
#pragma unroll
            for (int mt = 0; mt < 2; mt++)
#pragma unroll
                for (int nt = 0; nt < 4; nt++) {
                    mma16816(accg[mt][nt], ah[mt], bg[nt]);
                    mma16816(accu[mt][nt], ah[mt], bu[nt]);
                }
        }
        __syncthreads();
    }
#undef G1_LOAD

    // ---- epilogue: silu(gate)*up -> fp16 ----
#pragma unroll
    for (int mt = 0; mt < 2; mt++) {
        int rA = wm * 32 + mt * 16 + (lane >> 2);
        int sl0 = s_slot[rA], sl1 = s_slot[rA + 8];
#pragma unroll
        for (int nt = 0; nt < 4; nt++) {
            int col = j0 + wn * 32 + nt * 8 + (lane & 3) * 2;
#pragma unroll
            for (int hhalf = 0; hhalf < 2; hhalf++) {
                int sl = hhalf ? sl1 : sl0;
                if (sl < 0) continue;
                float g0 = accg[mt][nt][hhalf * 2], g1 = accg[mt][nt][hhalf * 2 + 1];
                float u0 = accu[mt][nt][hhalf * 2], u1 = accu[mt][nt][hhalf * 2 + 1];
                float a0 = (g0 * u0) / (1.0f + __expf(-g0));
                float a1 = (g1 * u1) / (1.0f + __expf(-g1));
                __half2 hh;
                hh.x = __float2half_rn(a0); hh.y = __float2half_rn(a1);
                *(__half2*)(g_act + (size_t)sl * ID + col) = hh;
            }
        }
    }
}

// ============================================================
// GEMM2 (mma.sync fp16, single term): per CTA 128 rows x 128 cols -> g_y fp32
// ============================================================
__global__ __launch_bounds__(256) void gemm2_tc() {
    int e = blockIdx.z;
    int n = (e < NE) ? g_count[e] : T;
    int row0 = blockIdx.x * BM;
    if (row0 >= n) return;
    int j0 = blockIdx.y * 128;
    int tid = threadIdx.x;
    int lane = tid & 31;
    int wid = tid >> 5;
    int wm = wid & 3;
    int wn = wid >> 2;           // 2 warps x 64 cols

    extern __shared__ char smem[];
    uint32_t sb = s2u(smem);
    int* s_arow = (int*)(smem + SM_TOK);
    int* s_slot = (int*)(smem + SM_SLOT);

    if (tid < BM) {
        int pos = row0 + tid;
        int slot;
        if (pos < n) slot = (e < NE) ? g_elist[e * T + pos] : (ROWS_R + pos);
        else         slot = -1;
        s_slot[tid] = slot;
        s_arow[tid] = (slot >= 0) ? slot
                                  : ((e < NE) ? g_elist[e * T + row0] : (ROWS_R + row0));
    }
    __syncthreads();

    int r0 = tid >> 2, f0 = tid & 3;
    int r1 = r0 + 64, f1 = f0;
    uint32_t off0 = (uint32_t)(r0 * RSB + f0 * 16);
    uint32_t off1 = (uint32_t)(r1 * RSB + f1 * 16);
    const char* pA0 = (const char*)(g_act + (size_t)s_arow[r0] * ID) + f0 * 16;
    const char* pA1 = (const char*)(g_act + (size_t)s_arow[r1] * ID) + f1 * 16;
    const char* pB0 = (const char*)(g_wd + ((size_t)e * HD + j0 + r0) * ID) + f0 * 16;
    const char* pB1 = (const char*)(g_wd + ((size_t)e * HD + j0 + r1) * ID) + f1 * 16;

#define G2_LOAD(bb) do { \
    CPA16((bb) + off0, pA0); CPA16((bb) + off1, pA1); \
    CPA16((bb) + PL + off0, pB0); CPA16((bb) + PL + off1, pB1); \
    pA0 += 64; pA1 += 64; pB0 += 64; pB1 += 64; \
    CP_COMMIT(); } while (0)

    float acc[2][8][4];
#pragma unroll
    for (int mt = 0; mt < 2; mt++)
#pragma unroll
        for (int nt = 0; nt < 8; nt++)
#pragma unroll
            for (int c = 0; c < 4; c++) acc[mt][nt][c] = 0.f;

    int lr = lane & 7;
    int aro = ((lane >> 3) & 1) * 8 + lr;
    int akb = (lane >> 4) * 16;
    int bro = ((lane >> 4) & 1) * 8 + lr;
    int bkb = ((lane >> 3) & 1) * 16;

    G2_LOAD(sb + SM_BUF0);

    for (int c = 0; c < NC2; c++) {
        if (c + 1 < NC2) G2_LOAD(sb + SM_BUF0 + ((c + 1) & 1) * BUFB);
        else CP_COMMIT();
        CP_WAIT1();
        __syncthreads();
        uint32_t bb = sb + SM_BUF0 + (c & 1) * BUFB;

#pragma unroll
        for (int ks = 0; ks < 2; ks++) {
            int kb = ks * 32;
            uint32_t ah[2][4];
#pragma unroll
            for (int mt = 0; mt < 2; mt++) {
                uint32_t ra = bb + (uint32_t)((wm * 32 + mt * 16 + aro) * RSB) + kb + akb;
                ldsm4(ah[mt], ra);
            }
            uint32_t bh[8][2];
#pragma unroll
            for (int p = 0; p < 4; p++) {
                uint32_t rb = bb + PL + (uint32_t)((wn * 64 + p * 16 + bro) * RSB) + kb + bkb;
                uint32_t rg[4];
                ldsm4(rg, rb);
                bh[2 * p][0] = rg[0]; bh[2 * p][1] = rg[1];
                bh[2 * p + 1][0] = rg[2]; bh[2 * p + 1][1] = rg[3];
            }
#pragma unroll
            for (int mt = 0; mt < 2; mt++)
#pragma unroll
                for (int nt = 0; nt < 8; nt++)
                    mma16816(acc[mt][nt], ah[mt], bh[nt]);
        }
        __syncthreads();
    }
#undef G2_LOAD

    // ---- epilogue: fp32 stores to g_y ----
#pragma unroll
    for (int mt = 0; mt < 2; mt++) {
        int rA = wm * 32 + mt * 16 + (lane >> 2);
        int sl0 = s_slot[rA], sl1 = s_slot[rA + 8];
#pragma unroll
        for (int nt = 0; nt < 8; nt++) {
            int col = j0 + wn * 64 + nt * 8 + (lane & 3) * 2;
            if (sl0 >= 0) {
                float2 v; v.x = acc[mt][nt][0]; v.y = acc[mt][nt][1];
                *(float2*)(g_y + (size_t)sl0 * HD + col) = v;
            }
            if (sl1 >= 0) {
                float2 v; v.x = acc[mt][nt][2]; v.y = acc[mt][nt][3];
                *(float2*)(g_y + (size_t)sl1 * HD + col) = v;
            }
        }
    }
}

// ============================================================
// combine: out[t] = w0*y[2t] + w1*y[2t+1] + y_shared[t]
// ============================================================
__global__ void combine_kernel(float* __restrict__ out) {
    int idx = blockIdx.x * blockDim.x + threadIdx.x;
    int t = idx / (HD / 4);
    int c = (idx % (HD / 4)) * 4;
    float w0 = g_wslot[2 * t];
    float w1 = g_wslot[2 * t + 1];
    float4 y0 = *(const float4*)(g_y + (size_t)(2 * t) * HD + c);
    float4 y1 = *(const float4*)(g_y + (size_t)(2 * t + 1) * HD + c);
    float4 ys = *(const float4*)(g_y + (size_t)(ROWS_R + t) * HD + c);
    float4 r;
    r.x = fmaf(w0, y0.x, fmaf(w1, y1.x, ys.x));
    r.y = fmaf(w0, y0.y, fmaf(w1, y1.y, ys.y));
    r.z = fmaf(w0, y0.z, fmaf(w1, y1.z, ys.z));
    r.w = fmaf(w0, y0.w, fmaf(w1, y1.w, ys.w));
    *(float4*)(out + (size_t)t * HD + c) = r;
}

// ============================================================
extern "C" void kernel_launch(void* const* d_in, const int* in_sizes, int n_in,
                              void* d_out, int out_size) {
    const float* x   = (const float*)d_in[0];
    const float* rw  = (const float*)d_in[1];
    const float* gw  = (const float*)d_in[2];
    const float* uw  = (const float*)d_in[3];
    const float* dw  = (const float*)d_in[4];
    const float* sgw = (const float*)d_in[5];
    const float* suw = (const float*)d_in[6];
    const float* sdw = (const float*)d_in[7];
    float* out = (float*)d_out;

    cudaFuncSetAttribute(gemm1_tc, cudaFuncAttributeMaxDynamicSharedMemorySize, SMEM_BYTES);
    cudaFuncSetAttribute(gemm2_tc, cudaFuncAttributeMaxDynamicSharedMemorySize, SMEM_BYTES);

    reset_kernel<<<1, 32>>>();
    convx_kernel<<<(T * HD / 4) / 256, 256>>>(x);
    convw_kernel<<<dim3(64, 32, 27), dim3(32, 8)>>>(gw, uw, dw, sgw, suw, sdw);
    router_kernel<<<T / 8, 256>>>(x, rw, out);
    finalize_kernel<<<1, 1>>>(out);
    gemm1_tc<<<dim3(T / BM, ID / 64, NE + 1), 256, SMEM_BYTES>>>();
    gemm2_tc<<<dim3(T / BM, HD / 128, NE + 1), 256, SMEM_BYTES>>>();
    combine_kernel<<<(T * HD / 4) / 256, 256>>>(out);
}

// round 11
// speedup vs baseline: 5.8337x; 1.3008x over previous
#include <cuda_runtime.h>
#include <cuda_fp16.h>
#include <math.h>
#include <cstdint>

#define T 4096
#define HD 1024
#define ID 2048
#define NE 8
#define NK 2
#define ROWS_R (T * NK)          /* 8192 routed rows (t*2+k) */
#define ROWS_ALL (ROWS_R + T)    /* + 4096 shared rows       */

#define OUT_AUX ((size_t)T * HD)
#define OUT_Z (OUT_AUX + 1)
#define OUT_LOGITS (OUT_Z + 1)

#define BM 128
#define BKC 32                   /* k-chunk (fp16 elems) = 64 bytes */
#define NC1 (HD / BKC)           /* 32 iters gemm1 */
#define NC2 (ID / BKC)           /* 64 iters gemm2 */
#define RSB 80                   /* smem row stride bytes (40 fp16) */

// smem plane: 128 rows * 80B = 10240; buffer = A | B  (2 planes)
#define PL 10240
#define BUFB (2 * PL)            /* 20480 */
#define SM_TOK 0
#define SM_SLOT 512
#define SM_BUF0 1024
#define SMEM_BYTES (1024 + 2 * BUFB)   /* 41984 */

typedef unsigned long long u64;

// ---------------- device scratch (static; no allocs allowed) ----------------
__device__ __half g_wg[(size_t)9 * ID * HD];    // gate  [e][n][k] fp16
__device__ __half g_wu[(size_t)9 * ID * HD];    // up    [e][n][k] fp16
__device__ __half g_wd[(size_t)9 * HD * ID];    // down  [e][n][k] fp16
__device__ __half g_x[(size_t)T * HD];          // x fp16
__device__ __half g_act[(size_t)ROWS_ALL * ID]; // silu(gate)*up fp16
__device__ float g_y[(size_t)ROWS_ALL * HD];
__device__ int   g_elist[NE * T];
__device__ int   g_count[NE];
__device__ float g_wslot[T * NK];
__device__ float g_probsum[NE];
__device__ float g_zsum;

// ---------------- PTX helpers (plain sm_103-safe) ----------------
static __device__ __forceinline__ uint32_t s2u(const void* p) {
    uint32_t a;
    asm("{ .reg .u64 t; cvta.to.shared.u64 t, %1; cvt.u32.u64 %0, t; }"
        : "=r"(a) : "l"(p));
    return a;
}

#define CPA16(sa, ga) \
    asm volatile("cp.async.cg.shared.global [%0], [%1], 16;" \
        :: "r"((uint32_t)(sa)), "l"(ga) : "memory")
#define CP_COMMIT() asm volatile("cp.async.commit_group;" ::: "memory")
#define CP_WAIT1()  asm volatile("cp.async.wait_group 1;" ::: "memory")

static __device__ __forceinline__ void ldsm4(uint32_t* r, uint32_t a) {
    asm volatile("ldmatrix.sync.aligned.m8n8.x4.shared.b16 {%0,%1,%2,%3}, [%4];"
        : "=r"(r[0]), "=r"(r[1]), "=r"(r[2]), "=r"(r[3]) : "r"(a));
}

static __device__ __forceinline__ void mma16816(float* d, const uint32_t* a,
                                                const uint32_t* b) {
    asm volatile(
        "mma.sync.aligned.m16n8k16.row.col.f32.f16.f16.f32 "
        "{%0,%1,%2,%3}, {%4,%5,%6,%7}, {%8,%9}, {%0,%1,%2,%3};"
        : "+f"(d[0]), "+f"(d[1]), "+f"(d[2]), "+f"(d[3])
        : "r"(a[0]), "r"(a[1]), "r"(a[2]), "r"(a[3]), "r"(b[0]), "r"(b[1]));
}

// ============================================================
__global__ void reset_kernel() {
    int i = threadIdx.x;
    if (i < NE) { g_count[i] = 0; g_probsum[i] = 0.f; }
    if (i == 0) g_zsum = 0.f;
}

// ============================================================
// convert + transpose ALL weights in one launch (vectorized):
// z in [0,27): mat = z/9 (0=gate,1=up,2=down), e = z%9
// src [K][N] fp32 -> dst [e][N][K] fp16
// ============================================================
__global__ void convw_kernel(const float* __restrict__ gw,
                             const float* __restrict__ uw,
                             const float* __restrict__ dw,
                             const float* __restrict__ sgw,
                             const float* __restrict__ suw,
                             const float* __restrict__ sdw) {
    int mat = blockIdx.z / 9;
    int e = blockIdx.z % 9;
    __half* dst;
    const float* src;
    int K, N, n0, k0;
    if (mat == 0) {
        dst = g_wg; src = (e < NE) ? gw + (size_t)e * HD * ID : sgw;
        K = HD; N = ID; n0 = blockIdx.x * 32; k0 = blockIdx.y * 32;
    } else if (mat == 1) {
        dst = g_wu; src = (e < NE) ? uw + (size_t)e * HD * ID : suw;
        K = HD; N = ID; n0 = blockIdx.x * 32; k0 = blockIdx.y * 32;
    } else {
        dst = g_wd; src = (e < NE) ? dw + (size_t)e * ID * HD : sdw;
        K = ID; N = HD; n0 = blockIdx.y * 32; k0 = blockIdx.x * 32;
    }
    __shared__ float tile[32][33];
    int tid = threadIdx.x;                 // 0..255
    // load phase: 32 rows x 8 float4 per row
    {
        int row = tid >> 3, f4 = tid & 7;
        float4 v = *(const float4*)(src + (size_t)(k0 + row) * N + n0 + f4 * 4);
        tile[row][f4 * 4 + 0] = v.x;
        tile[row][f4 * 4 + 1] = v.y;
        tile[row][f4 * 4 + 2] = v.z;
        tile[row][f4 * 4 + 3] = v.w;
    }
    __syncthreads();
    // store phase: 32 n-rows x 8 segs of 4 k-values (uint2 = 4 fp16)
    {
        int nr = tid >> 3, seg = tid & 7;
        int k = seg * 4;
        __half2 a, b;
        a.x = __float2half_rn(tile[k + 0][nr]);
        a.y = __float2half_rn(tile[k + 1][nr]);
        b.x = __float2half_rn(tile[k + 2][nr]);
        b.y = __float2half_rn(tile[k + 3][nr]);
        uint2 pk;
        pk.x = *(uint32_t*)&a;
        pk.y = *(uint32_t*)&b;
        *(uint2*)(dst + (size_t)e * K * N + (size_t)(n0 + nr) * K + k0 + k) = pk;
    }
}

// ============================================================
// router (+ fused x->fp16 conversion): 8 warps/block, one token/warp.
// rw staged in smem with stride-9 rows (conflict-free); scalar coalesced
// x loads; probsum/zsum aggregated in smem before global atomics.
// ============================================================
__global__ void router_kernel(const float* __restrict__ x,
                              const float* __restrict__ rw,
                              float* __restrict__ out) {
    int tid = threadIdx.x;
    int warp = tid >> 5;
    int lane = tid & 31;
    int t = blockIdx.x * 8 + warp;

    __shared__ float srw[HD * 9];          // 36864 B, row h at srw[h*9]
    __shared__ float sp[NE];
    __shared__ float sz;

    // stage rw: 2048 float4 = 8 per thread
#pragma unroll
    for (int i = 0; i < 8; i++) {
        int f = tid + i * 256;             // float4 index
        float4 v = ((const float4*)rw)[f];
        int h = f >> 1;
        int e0 = (f & 1) * 4;
        srw[h * 9 + e0 + 0] = v.x;
        srw[h * 9 + e0 + 1] = v.y;
        srw[h * 9 + e0 + 2] = v.z;
        srw[h * 9 + e0 + 3] = v.w;
    }
    if (tid < NE) sp[tid] = 0.f;
    if (tid == NE) sz = 0.f;
    __syncthreads();

    const float* xr = x + (size_t)t * HD;
    __half* gx = g_x + (size_t)t * HD;
    float acc[NE];
#pragma unroll
    for (int e = 0; e < NE; e++) acc[e] = 0.f;
#pragma unroll 8
    for (int i = 0; i < 32; i++) {
        int h = lane + i * 32;
        float xv = xr[h];
        gx[h] = __float2half_rn(xv);       // fused convx
        const float* r = &srw[h * 9];
#pragma unroll
        for (int e = 0; e < NE; e++) acc[e] = fmaf(xv, r[e], acc[e]);
    }
#pragma unroll
    for (int off = 16; off; off >>= 1) {
#pragma unroll
        for (int e = 0; e < NE; e++)
            acc[e] += __shfl_xor_sync(0xffffffffu, acc[e], off);
    }

    if (lane == 0) {
        float m = acc[0];
#pragma unroll
        for (int e = 1; e < NE; e++) m = fmaxf(m, acc[e]);
        float s = 0.f;
#pragma unroll
        for (int e = 0; e < NE; e++) s += expf(acc[e] - m);
        float lse = m + logf(s);
        float p[NE];
#pragma unroll
        for (int e = 0; e < NE; e++) p[e] = expf(acc[e] - lse);

        // top-2, first-occurrence tie break (matches jax.lax.top_k)
        int i0 = 0;
#pragma unroll
        for (int e = 1; e < NE; e++) if (p[e] > p[i0]) i0 = e;
        int i1 = (i0 == 0) ? 1 : 0;
#pragma unroll
        for (int e = 0; e < NE; e++) if (e != i1 && e != i0 && p[e] > p[i1]) i1 = e;

        float sum2 = p[i0] + p[i1];
        g_wslot[2 * t]     = p[i0] / sum2;
        g_wslot[2 * t + 1] = p[i1] / sum2;

        int pos0 = atomicAdd(&g_count[i0], 1);
        g_elist[i0 * T + pos0] = 2 * t;
        int pos1 = atomicAdd(&g_count[i1], 1);
        g_elist[i1 * T + pos1] = 2 * t + 1;

#pragma unroll
        for (int e = 0; e < NE; e++) {
            out[OUT_LOGITS + (size_t)t * NE + e] = acc[e];
            atomicAdd(&sp[e], p[e]);
        }
        atomicAdd(&sz, lse * lse);
    }
    __syncthreads();
    if (tid < NE) atomicAdd(&g_probsum[tid], sp[tid]);
    if (tid == NE) atomicAdd(&g_zsum, sz);
}

__global__ void finalize_kernel(float* __restrict__ out) {
    if (threadIdx.x == 0) {
        float aux = 0.f;
#pragma unroll
        for (int e = 0; e < NE; e++)
            aux += ((float)g_count[e] / (2.0f * (float)T)) * (g_probsum[e] / (float)T);
        out[OUT_AUX] = (float)NE * aux;
        out[OUT_Z] = g_zsum / (float)T;
    }
}

// ============================================================
// GEMM1 (mma.sync fp16, single term): per CTA 128 rows x 64 cols of
// BOTH gate and up; fused SiLU epilogue -> g_act fp16.
// smem buffer: A | B(gate rows 0-63, up rows 64-127)
// ============================================================
__global__ __launch_bounds__(256) void gemm1_tc() {
    int e = blockIdx.z;
    int n = (e < NE) ? g_count[e] : T;
    int row0 = blockIdx.x * BM;
    if (row0 >= n) return;
    int j0 = blockIdx.y * 64;
    int tid = threadIdx.x;
    int lane = tid & 31;
    int wid = tid >> 5;
    int wm = wid & 3;            // M: 4 warps
    int wn = wid >> 2;           // N: 2 warps (32 cols each)

    extern __shared__ char smem[];
    uint32_t sb = s2u(smem);
    int* s_tok = (int*)(smem + SM_TOK);
    int* s_slot = (int*)(smem + SM_SLOT);

    if (tid < BM) {
        int pos = row0 + tid;
        int slot, tok;
        if (pos < n) {
            if (e < NE) { slot = g_elist[e * T + pos]; tok = slot >> 1; }
            else        { slot = ROWS_R + pos;         tok = pos; }
        } else {
            slot = -1;
            tok = (e < NE) ? (g_elist[e * T + row0] >> 1) : row0;
        }
        s_slot[tid] = slot;
        s_tok[tid] = tok;
    }
    __syncthreads();

    // loaders: 4 x 16B per thread per chunk (A: 2, B: 2)
    int r0 = tid >> 2, f0 = tid & 3;
    int r1 = r0 + 64, f1 = f0;
    uint32_t off0 = (uint32_t)(r0 * RSB + f0 * 16);
    uint32_t off1 = (uint32_t)(r1 * RSB + f1 * 16);
    const char* pA0 = (const char*)(g_x + (size_t)s_tok[r0] * HD) + f0 * 16;
    const char* pA1 = (const char*)(g_x + (size_t)s_tok[r1] * HD) + f1 * 16;
    // B plane rows: r0 (0-63) -> gate row j0+r0 ; r1 (64-127) -> up row j0+r1-64
    const char* pB0 = (const char*)(g_wg + ((size_t)e * ID + j0 + r0) * HD) + f0 * 16;
    const char* pB1 = (const char*)(g_wu + ((size_t)e * ID + j0 + r1 - 64) * HD) + f1 * 16;

#define G1_LOAD(bb) do { \
    CPA16((bb) + off0, pA0); CPA16((bb) + off1, pA1); \
    CPA16((bb) + PL + off0, pB0); CPA16((bb) + PL + off1, pB1); \
    pA0 += 64; pA1 += 64; pB0 += 64; pB1 += 64; \
    CP_COMMIT(); } while (0)

    float accg[2][4][4], accu[2][4][4];
#pragma unroll
    for (int mt = 0; mt < 2; mt++)
#pragma unroll
        for (int nt = 0; nt < 4; nt++)
#pragma unroll
            for (int c = 0; c < 4; c++) { accg[mt][nt][c] = 0.f; accu[mt][nt][c] = 0.f; }

    int lr = lane & 7;
    int aro = ((lane >> 3) & 1) * 8 + lr;     // A row-in-16
    int akb = (lane >> 4) * 16;               // A k-byte half
    int bro = ((lane >> 4) & 1) * 8 + lr;     // B row-in-16
    int bkb = ((lane >> 3) & 1) * 16;         // B k-byte half

    G1_LOAD(sb + SM_BUF0);

    for (int c = 0; c < NC1; c++) {
        if (c + 1 < NC1) G1_LOAD(sb + SM_BUF0 + ((c + 1) & 1) * BUFB);
        else CP_COMMIT();
        CP_WAIT1();
        __syncthreads();
        uint32_t bb = sb + SM_BUF0 + (c & 1) * BUFB;

#pragma unroll
        for (int ks = 0; ks < 2; ks++) {
            int kb = ks * 32;
            uint32_t ah[2][4];
#pragma unroll
            for (int mt = 0; mt < 2; mt++) {
                uint32_t ra = bb + (uint32_t)((wm * 32 + mt * 16 + aro) * RSB) + kb + akb;
                ldsm4(ah[mt], ra);
            }
            uint32_t bg[4][2], bu[4][2];
#pragma unroll
            for (int p = 0; p < 2; p++) {
                uint32_t rb = bb + PL + (uint32_t)((wn * 32 + p * 16 + bro) * RSB) + kb + bkb;
                uint32_t rg[4];
                ldsm4(rg, rb);
                bg[2 * p][0] = rg[0]; bg[2 * p][1] = rg[1];
                bg[2 * p + 1][0] = rg[2]; bg[2 * p + 1][1] = rg[3];
                ldsm4(rg, rb + 64 * RSB);
                bu[2 * p][0] = rg[0]; bu[2 * p][1] = rg[1];
                bu[2 * p + 1][0] = rg[2]; bu[2 * p + 1][1] = rg[3];
            }
#pragma unroll
            for (int mt = 0; mt < 2; mt++)
#pragma unroll
                for (int nt = 0; nt < 4; nt++) {
                    mma16816(accg[mt][nt], ah[mt], bg[nt]);
                    mma16816(accu[mt][nt], ah[mt], bu[nt]);
                }
        }
        __syncthreads();
    }
#undef G1_LOAD

    // ---- epilogue: silu(gate)*up -> fp16 ----
#pragma unroll
    for (int mt = 0; mt < 2; mt++) {
        int rA = wm * 32 + mt * 16 + (lane >> 2);
        int sl0 = s_slot[rA], sl1 = s_slot[rA + 8];
#pragma unroll
        for (int nt = 0; nt < 4; nt++) {
            int col = j0 + wn * 32 + nt * 8 + (lane & 3) * 2;
#pragma unroll
            for (int hhalf = 0; hhalf < 2; hhalf++) {
                int sl = hhalf ? sl1 : sl0;
                if (sl < 0) continue;
                float g0 = accg[mt][nt][hhalf * 2], g1 = accg[mt][nt][hhalf * 2 + 1];
                float u0 = accu[mt][nt][hhalf * 2], u1 = accu[mt][nt][hhalf * 2 + 1];
                float a0 = (g0 * u0) / (1.0f + __expf(-g0));
                float a1 = (g1 * u1) / (1.0f + __expf(-g1));
                __half2 hh;
                hh.x = __float2half_rn(a0); hh.y = __float2half_rn(a1);
                *(__half2*)(g_act + (size_t)sl * ID + col) = hh;
            }
        }
    }
}

// ============================================================
// GEMM2 (mma.sync fp16, single term): per CTA 128 rows x 128 cols -> g_y fp32
// ============================================================
__global__ __launch_bounds__(256) void gemm2_tc() {
    int e = blockIdx.z;
    int n = (e < NE) ? g_count[e] : T;
    int row0 = blockIdx.x * BM;
    if (row0 >= n) return;
    int j0 = blockIdx.y * 128;
    int tid = threadIdx.x;
    int lane = tid & 31;
    int wid = tid >> 5;
    int wm = wid & 3;
    int wn = wid >> 2;           // 2 warps x 64 cols

    extern __shared__ char smem[];
    uint32_t sb = s2u(smem);
    int* s_arow = (int*)(smem + SM_TOK);
    int* s_slot = (int*)(smem + SM_SLOT);

    if (tid < BM) {
        int pos = row0 + tid;
        int slot;
        if (pos < n) slot = (e < NE) ? g_elist[e * T + pos] : (ROWS_R + pos);
        else         slot = -1;
        s_slot[tid] = slot;
        s_arow[tid] = (slot >= 0) ? slot
                                  : ((e < NE) ? g_elist[e * T + row0] : (ROWS_R + row0));
    }
    __syncthreads();

    int r0 = tid >> 2, f0 = tid & 3;
    int r1 = r0 + 64, f1 = f0;
    uint32_t off0 = (uint32_t)(r0 * RSB + f0 * 16);
    uint32_t off1 = (uint32_t)(r1 * RSB + f1 * 16);
    const char* pA0 = (const char*)(g_act + (size_t)s_arow[r0] * ID) + f0 * 16;
    const char* pA1 = (const char*)(g_act + (size_t)s_arow[r1] * ID) + f1 * 16;
    const char* pB0 = (const char*)(g_wd + ((size_t)e * HD + j0 + r0) * ID) + f0 * 16;
    const char* pB1 = (const char*)(g_wd + ((size_t)e * HD + j0 + r1) * ID) + f1 * 16;

#define G2_LOAD(bb) do { \
    CPA16((bb) + off0, pA0); CPA16((bb) + off1, pA1); \
    CPA16((bb) + PL + off0, pB0); CPA16((bb) + PL + off1, pB1); \
    pA0 += 64; pA1 += 64; pB0 += 64; pB1 += 64; \
    CP_COMMIT(); } while (0)

    float acc[2][8][4];
#pragma unroll
    for (int mt = 0; mt < 2; mt++)
#pragma unroll
        for (int nt = 0; nt < 8; nt++)
#pragma unroll
            for (int c = 0; c < 4; c++) acc[mt][nt][c] = 0.f;

    int lr = lane & 7;
    int aro = ((lane >> 3) & 1) * 8 + lr;
    int akb = (lane >> 4) * 16;
    int bro = ((lane >> 4) & 1) * 8 + lr;
    int bkb = ((lane >> 3) & 1) * 16;

    G2_LOAD(sb + SM_BUF0);

    for (int c = 0; c < NC2; c++) {
        if (c + 1 < NC2) G2_LOAD(sb + SM_BUF0 + ((c + 1) & 1) * BUFB);
        else CP_COMMIT();
        CP_WAIT1();
        __syncthreads();
        uint32_t bb = sb + SM_BUF0 + (c & 1) * BUFB;

#pragma unroll
        for (int ks = 0; ks < 2; ks++) {
            int kb = ks * 32;
            uint32_t ah[2][4];
#pragma unroll
            for (int mt = 0; mt < 2; mt++) {
                uint32_t ra = bb + (uint32_t)((wm * 32 + mt * 16 + aro) * RSB) + kb + akb;
                ldsm4(ah[mt], ra);
            }
            uint32_t bh[8][2];
#pragma unroll
            for (int p = 0; p < 4; p++) {
                uint32_t rb = bb + PL + (uint32_t)((wn * 64 + p * 16 + bro) * RSB) + kb + bkb;
                uint32_t rg[4];
                ldsm4(rg, rb);
                bh[2 * p][0] = rg[0]; bh[2 * p][1] = rg[1];
                bh[2 * p + 1][0] = rg[2]; bh[2 * p + 1][1] = rg[3];
            }
#pragma unroll
            for (int mt = 0; mt < 2; mt++)
#pragma unroll
                for (int nt = 0; nt < 8; nt++)
                    mma16816(acc[mt][nt], ah[mt], bh[nt]);
        }
        __syncthreads();
    }
#undef G2_LOAD

    // ---- epilogue: fp32 stores to g_y ----
#pragma unroll
    for (int mt = 0; mt < 2; mt++) {
        int rA = wm * 32 + mt * 16 + (lane >> 2);
        int sl0 = s_slot[rA], sl1 = s_slot[rA + 8];
#pragma unroll
        for (int nt = 0; nt < 8; nt++) {
            int col = j0 + wn * 64 + nt * 8 + (lane & 3) * 2;
            if (sl0 >= 0) {
                float2 v; v.x = acc[mt][nt][0]; v.y = acc[mt][nt][1];
                *(float2*)(g_y + (size_t)sl0 * HD + col) = v;
            }
            if (sl1 >= 0) {
                float2 v; v.x = acc[mt][nt][2]; v.y = acc[mt][nt][3];
                *(float2*)(g_y + (size_t)sl1 * HD + col) = v;
            }
        }
    }
}

// ============================================================
// combine: out[t] = w0*y[2t] + w1*y[2t+1] + y_shared[t]
// ============================================================
__global__ void combine_kernel(float* __restrict__ out) {
    int idx = blockIdx.x * blockDim.x + threadIdx.x;
    int t = idx / (HD / 4);
    int c = (idx % (HD / 4)) * 4;
    float w0 = g_wslot[2 * t];
    float w1 = g_wslot[2 * t + 1];
    float4 y0 = *(const float4*)(g_y + (size_t)(2 * t) * HD + c);
    float4 y1 = *(const float4*)(g_y + (size_t)(2 * t + 1) * HD + c);
    float4 ys = *(const float4*)(g_y + (size_t)(ROWS_R + t) * HD + c);
    float4 r;
    r.x = fmaf(w0, y0.x, fmaf(w1, y1.x, ys.x));
    r.y = fmaf(w0, y0.y, fmaf(w1, y1.y, ys.y));
    r.z = fmaf(w0, y0.z, fmaf(w1, y1.z, ys.z));
    r.w = fmaf(w0, y0.w, fmaf(w1, y1.w, ys.w));
    *(float4*)(out + (size_t)t * HD + c) = r;
}

// ============================================================
extern "C" void kernel_launch(void* const* d_in, const int* in_sizes, int n_in,
                              void* d_out, int out_size) {
    const float* x   = (const float*)d_in[0];
    const float* rw  = (const float*)d_in[1];
    const float* gw  = (const float*)d_in[2];
    const float* uw  = (const float*)d_in[3];
    const float* dw  = (const float*)d_in[4];
    const float* sgw = (const float*)d_in[5];
    const float* suw = (const float*)d_in[6];
    const float* sdw = (const float*)d_in[7];
    float* out = (float*)d_out;

    cudaFuncSetAttribute(gemm1_tc, cudaFuncAttributeMaxDynamicSharedMemorySize, SMEM_BYTES);
    cudaFuncSetAttribute(gemm2_tc, cudaFuncAttributeMaxDynamicSharedMemorySize, SMEM_BYTES);

    reset_kernel<<<1, 32>>>();
    convw_kernel<<<dim3(64, 32, 27), 256>>>(gw, uw, dw, sgw, suw, sdw);
    router_kernel<<<T / 8, 256>>>(x, rw, out);
    finalize_kernel<<<1, 1>>>(out);
    gemm1_tc<<<dim3(T / BM, ID / 64, NE + 1), 256, SMEM_BYTES>>>();
    gemm2_tc<<<dim3(T / BM, HD / 128, NE + 1), 256, SMEM_BYTES>>>();
    combine_kernel<<<(T * HD / 4) / 256, 256>>>(out);
}